// round 14
// baseline (speedup 1.0000x reference)
#include <cuda_runtime.h>
#include <cuda_bf16.h>
#include <math.h>
#include <stdint.h>

// Problem dims (fixed by setup_inputs)
#define Bz 2
#define Sz 2048
#define Dz 1024
#define Tz 4096           // B*S
#define Hz 16
#define DHz 64
#define HIz 4
#define DIz 64
#define TKz 512
#define Ez 4
#define DFz 4096

typedef __nv_bfloat16 bf16;

// ---------------- scratch (device globals; no allocation allowed) --------------
__device__ float g_xn [Tz*Dz];
__device__ float g_q  [Tz*Dz];
__device__ float g_qI [Tz*HIz*DIz];
__device__ float g_kI [Tz*DIz];
__device__ float g_wI [Tz*HIz];
__device__ float g_sc [(size_t)Bz*Sz*Sz];
__device__ int   g_selidx[(size_t)Tz*TKz];
__device__ int   g_selcnt[Tz];
__device__ float g_x2 [Tz*Dz];
__device__ float g_xn2[Tz*Dz];
__device__ float g_wd [Tz*Ez];
__device__ float g_pr [Tz*Ez];
__device__ int   g_ecnt[Ez];
__device__ int   g_elist[Ez*Tz];
__device__ float g_ffe[(size_t)Ez*Tz*Dz];

// bf16 operands: split storage is [hi|lo] (2K); GEMM remaps k-blocks to get
// the 3-term product Ahi*Bhi + Ahi*Blo + Alo*Bhi.
__device__ bf16 g_kvb  [(size_t)2*Tz*Dz];
__device__ bf16 g_xnx  [(size_t)Tz*2*Dz];
__device__ bf16 g_xn2x [(size_t)Tz*2*Dz];
__device__ bf16 g_aox  [(size_t)Tz*2*Dz];
__device__ bf16 g_hx   [(size_t)Ez*Tz*2*DFz];
__device__ bf16 g_wqkvx[(size_t)3*2*Dz*Dz];
__device__ bf16 g_wox  [2*Dz*Dz];
__device__ bf16 g_iwqx [2*Dz*HIz*DIz];
__device__ bf16 g_w1x  [(size_t)Ez*2*Dz*DFz];
__device__ bf16 g_w2x  [(size_t)Ez*2*DFz*Dz];

// ---------------- helpers ------------------------------------------------------
__device__ __forceinline__ float gelu_f(float x) {
    float x3 = x * x * x;
    return 0.5f * x * (1.0f + tanhf(0.7978845608028654f * (x + 0.044715f * x3)));
}
__device__ __forceinline__ uint32_t smem_u32(const void* p) {
    return (uint32_t)__cvta_generic_to_shared(p);
}
__device__ __forceinline__ void ldsm4(uint32_t& r0, uint32_t& r1, uint32_t& r2,
                                      uint32_t& r3, uint32_t a) {
    asm volatile("ldmatrix.sync.aligned.m8n8.x4.shared.b16 {%0,%1,%2,%3}, [%4];\n"
                 : "=r"(r0), "=r"(r1), "=r"(r2), "=r"(r3) : "r"(a));
}
__device__ __forceinline__ void ldsm4t(uint32_t& r0, uint32_t& r1, uint32_t& r2,
                                       uint32_t& r3, uint32_t a) {
    asm volatile("ldmatrix.sync.aligned.m8n8.x4.trans.shared.b16 {%0,%1,%2,%3}, [%4];\n"
                 : "=r"(r0), "=r"(r1), "=r"(r2), "=r"(r3) : "r"(a));
}
__device__ __forceinline__ void mma_bf16(float c[4], uint32_t a0, uint32_t a1,
                                         uint32_t a2, uint32_t a3,
                                         uint32_t b0, uint32_t b1) {
    asm volatile("mma.sync.aligned.m16n8k16.row.col.f32.bf16.bf16.f32 "
                 "{%0,%1,%2,%3}, {%4,%5,%6,%7}, {%8,%9}, {%0,%1,%2,%3};\n"
                 : "+f"(c[0]), "+f"(c[1]), "+f"(c[2]), "+f"(c[3])
                 : "r"(a0), "r"(a1), "r"(a2), "r"(a3), "r"(b0), "r"(b1));
}
#define CPA16(dst, src) \
    asm volatile("cp.async.cg.shared.global [%0], [%1], 16;\n" :: "r"(dst), "l"(src))
#define CPA_COMMIT() asm volatile("cp.async.commit_group;\n" ::)
#define CPA_WAIT1()  asm volatile("cp.async.wait_group 1;\n" ::)

// smem layout constants for hgemm (3-stage)
#define AS_BYTES (128 * 40 * 2)     // 10240
#define BS_BYTES (32 * 136 * 2)     // 8704
#define STAGE_BYTES (AS_BYTES + BS_BYTES)
#define HG_SMEM (3 * STAGE_BYTES)   // 56832

// ---------------- rmsnorm (fp32 out optional + bf16 [hi|lo] out) ---------------
__global__ void rmsnorm2_kernel(const float* __restrict__ x, const float* __restrict__ w,
                                float* __restrict__ y, bf16* __restrict__ yx) {
    int t = blockIdx.x;
    int tid = threadIdx.x;
    const float* xr = x + (size_t)t * Dz;
    float s = 0.f;
    for (int i = tid; i < Dz; i += 256) { float v = xr[i]; s += v * v; }
    __shared__ float red[256];
    red[tid] = s; __syncthreads();
    for (int off = 128; off; off >>= 1) {
        if (tid < off) red[tid] += red[tid + off];
        __syncthreads();
    }
    float inv = rsqrtf(red[0] * (1.0f / Dz) + 1e-6f);
    bf16* yr = yx + (size_t)t * 2 * Dz;
    for (int i = tid; i < Dz; i += 256) {
        float v = xr[i] * inv * w[i];
        if (y) y[(size_t)t * Dz + i] = v;
        bf16 hi = __float2bfloat16(v);
        bf16 lo = __float2bfloat16(v - __bfloat162float(hi));
        yr[i] = hi;
        yr[Dz + i] = lo;
    }
}

// ---------------- weight split: [K][N] fp32 -> [2K][N] bf16 [hi;lo] ------------
// N power of two, logN >= 4 (16 consecutive elements never cross a row).
// Each thread: 4 outstanding float4 loads (MLP=4), 2x16B stores per stream.
__global__ void convw_kernel(const float* __restrict__ src, bf16* __restrict__ dst,
                             int K, int logN) {
    unsigned nmask = (unsigned)((1 << logN) - 1);
    size_t total16 = ((size_t)K << logN) >> 4;
    for (size_t g = blockIdx.x * blockDim.x + threadIdx.x; g < total16;
         g += (size_t)gridDim.x * blockDim.x) {
        float4 a[4];
#pragma unroll
        for (int j = 0; j < 4; j++) a[j] = ((const float4*)src)[g * 4 + j];
        __align__(16) bf16 hv[16], lv[16];
#pragma unroll
        for (int j = 0; j < 4; j++) {
            const float* f = (const float*)&a[j];
#pragma unroll
            for (int q = 0; q < 4; q++) {
                bf16 hi = __float2bfloat16(f[q]);
                hv[j * 4 + q] = hi;
                lv[j * 4 + q] = __float2bfloat16(f[q] - __bfloat162float(hi));
            }
        }
        size_t base = g << 4;
        int k = (int)(base >> logN);
        int n = (int)(base & nmask);
        bf16* dh = &dst[((size_t)k << logN) + n];
        bf16* dl = &dst[((size_t)(K + k) << logN) + n];
        ((float4*)dh)[0] = ((float4*)hv)[0];
        ((float4*)dh)[1] = ((float4*)hv)[1];
        ((float4*)dl)[0] = ((float4*)lv)[0];
        ((float4*)dl)[1] = ((float4*)lv)[1];
    }
}

// ---------------- bf16 tensor-core GEMM (z-batched, 3-term remap, 3-stage) ------
// Logical C[M,N] = A[M,3*Kthird] x B[3*Kthird,N] stored [hi|lo] (2*Kthird);
// k-block kt maps: A-block = kt<KB?kt:kt-KB, B-block = kt<2KB?kt:kt-2KB.
// 128 threads, 4 warps, warp tile 64x64, CTA tile 128x128. Dynamic smem, 3 stages.
// EPI 0: Cf = val
// EPI 1: Cf = val + resid
// EPI 2: gather A rows via elist[z]; Cb+z*c_zs [hi|lo] (stride 2N) of gelu(val+bias)
// EPI 3: scatter: (Cf+z*c_zs)[tok*N+c] = wdv[tok*Ez+z]*(val+bias[c])
// EPI 5: QKV: z==0 -> Cf fp32; z>=1 -> (Cb+(z-1)*c_zs) plain bf16
template<int EPI>
__global__ void __launch_bounds__(128, 2)
hgemm_kernel(const bf16* __restrict__ A, const bf16* __restrict__ B,
             float* __restrict__ Cf, bf16* __restrict__ Cb,
             int M, int N, int Kthird,
             const float* __restrict__ bias, const float* __restrict__ resid,
             const float* __restrict__ wdv,
             const int* __restrict__ elist, const int* __restrict__ ecnt,
             size_t a_zs, size_t b_zs, size_t c_zs, int bias_zs) {
    int z = blockIdx.z;
    int bm = blockIdx.y * 128, bn = blockIdx.x * 128;
    int cnt = M;
    if (ecnt) {
        cnt = ecnt[z];
        int padded = (cnt + 127) & ~127;
        if (bm >= padded) return;
    }
    A += (size_t)z * a_zs;
    B += (size_t)z * b_zs;
    if (bias) bias += (size_t)z * bias_zs;
    const int* lst = elist ? elist + (size_t)z * Tz : nullptr;

    extern __shared__ __align__(16) char dynsmem[];
    typedef bf16 AsT[128][40];
    typedef bf16 BsT[32][136];
    AsT* Asp[3]; BsT* Bsp[3];
#pragma unroll
    for (int s3 = 0; s3 < 3; s3++) {
        Asp[s3] = (AsT*)(dynsmem + s3 * STAGE_BYTES);
        Bsp[s3] = (BsT*)(dynsmem + s3 * STAGE_BYTES + AS_BYTES);
    }
    int tid = threadIdx.x;
    int warp = tid >> 5, lane = tid & 31;
    int wm = (warp & 1) * 64, wn = (warp >> 1) * 64;

    const int KB = Kthird >> 5;
    const int KT = 3 * KB;
    const int AS = 2 * Kthird;

    int arow = tid >> 2, acol = (tid & 3) * 8;
    int brow = tid >> 4, bcol = (tid & 15) * 8;
    const bf16* Ag[4];
#pragma unroll
    for (int j = 0; j < 4; j++) {
        int r = bm + arow + 32 * j;
        if (EPI == 2) r = lst[r];
        Ag[j] = A + (size_t)r * AS + acol;
    }
    const bf16* Bg = B + (size_t)brow * N + bn + bcol;

    float c[4][8][4];
#pragma unroll
    for (int mi = 0; mi < 4; mi++)
#pragma unroll
        for (int ni = 0; ni < 8; ni++)
#pragma unroll
            for (int j = 0; j < 4; j++) c[mi][ni][j] = 0.f;

    // prologue: issue tiles 0 and 1 (separate groups)
    {
        bf16 (*As0)[40] = *Asp[0];
        bf16 (*Bs0)[136] = *Bsp[0];
#pragma unroll
        for (int j = 0; j < 4; j++)
            CPA16(smem_u32(&As0[arow + 32 * j][acol]), Ag[j]);
#pragma unroll
        for (int j = 0; j < 4; j++)
            CPA16(smem_u32(&Bs0[brow + 8 * j][bcol]), Bg + (size_t)(8 * j) * N);
        CPA_COMMIT();
        int ak = (1 < KB) ? 1 : 1 - KB;           // KB >= 8 always, so ak = 1
        int bk = 1;                               // 1 < 2*KB always
        bf16 (*As1)[40] = *Asp[1];
        bf16 (*Bs1)[136] = *Bsp[1];
#pragma unroll
        for (int j = 0; j < 4; j++)
            CPA16(smem_u32(&As1[arow + 32 * j][acol]), Ag[j] + ak * 32);
#pragma unroll
        for (int j = 0; j < 4; j++)
            CPA16(smem_u32(&Bs1[brow + 8 * j][bcol]), Bg + (size_t)(bk * 32 + 8 * j) * N);
        CPA_COMMIT();
    }
    for (int kt = 0; kt < KT; kt++) {
        CPA_WAIT1();
        __syncthreads();
        // issue tile kt+2 (or commit empty group to keep counts uniform)
        if (kt + 2 < KT) {
            int k2 = kt + 2;
            int ak = (k2 < KB) ? k2 : k2 - KB;
            int bk = (k2 < 2 * KB) ? k2 : k2 - 2 * KB;
            int nb = k2 - (k2 / 3) * 3;           // (kt+2)%3
            bf16 (*Asn)[40] = *Asp[nb];
            bf16 (*Bsn)[136] = *Bsp[nb];
#pragma unroll
            for (int j = 0; j < 4; j++)
                CPA16(smem_u32(&Asn[arow + 32 * j][acol]), Ag[j] + ak * 32);
#pragma unroll
            for (int j = 0; j < 4; j++)
                CPA16(smem_u32(&Bsn[brow + 8 * j][bcol]),
                      Bg + (size_t)(bk * 32 + 8 * j) * N);
        }
        CPA_COMMIT();
        int buf = kt - (kt / 3) * 3;              // kt%3
        bf16 (*Asb)[40] = *Asp[buf];
        bf16 (*Bsb)[136] = *Bsp[buf];
#pragma unroll
        for (int kk = 0; kk < 32; kk += 16) {
            uint32_t a[4][4], b[8][2];
#pragma unroll
            for (int mi = 0; mi < 4; mi++) {
                uint32_t addr = smem_u32(
                    &Asb[wm + mi * 16 + (lane & 15)][kk + ((lane >> 4) << 3)]);
                ldsm4(a[mi][0], a[mi][1], a[mi][2], a[mi][3], addr);
            }
#pragma unroll
            for (int nj = 0; nj < 4; nj++) {
                uint32_t addr = smem_u32(
                    &Bsb[kk + (lane & 15)][wn + nj * 16 + ((lane >> 4) << 3)]);
                ldsm4t(b[2 * nj][0], b[2 * nj][1], b[2 * nj + 1][0], b[2 * nj + 1][1], addr);
            }
#pragma unroll
            for (int mi = 0; mi < 4; mi++)
#pragma unroll
                for (int ni = 0; ni < 8; ni++)
                    mma_bf16(c[mi][ni], a[mi][0], a[mi][1], a[mi][2], a[mi][3],
                             b[ni][0], b[ni][1]);
        }
    }

#pragma unroll
    for (int mi = 0; mi < 4; mi++) {
#pragma unroll
        for (int rr = 0; rr < 2; rr++) {
            int r = bm + wm + mi * 16 + (lane >> 2) + rr * 8;
            if (EPI == 3) {
                if (r < cnt) {
                    int tok = lst[r];
                    float rsc = wdv[(size_t)tok * Ez + z];
                    float* dst = Cf + (size_t)z * c_zs;
#pragma unroll
                    for (int ni = 0; ni < 8; ni++)
#pragma unroll
                        for (int cc = 0; cc < 2; cc++) {
                            int col = bn + wn + ni * 8 + (lane & 3) * 2 + cc;
                            dst[(size_t)tok * N + col] =
                                rsc * (c[mi][ni][rr * 2 + cc] + bias[col]);
                        }
                }
            } else if (EPI == 5) {
                if (z == 0) {
#pragma unroll
                    for (int ni = 0; ni < 8; ni++)
#pragma unroll
                        for (int cc = 0; cc < 2; cc++) {
                            int col = bn + wn + ni * 8 + (lane & 3) * 2 + cc;
                            Cf[(size_t)r * N + col] = c[mi][ni][rr * 2 + cc];
                        }
                } else {
                    bf16* dst = Cb + (size_t)(z - 1) * c_zs;
#pragma unroll
                    for (int ni = 0; ni < 8; ni++) {
                        int colb = bn + wn + ni * 8 + (lane & 3) * 2;
                        __nv_bfloat162 p;
                        p.x = __float2bfloat16(c[mi][ni][rr * 2]);
                        p.y = __float2bfloat16(c[mi][ni][rr * 2 + 1]);
                        *(__nv_bfloat162*)&dst[(size_t)r * N + colb] = p;
                    }
                }
            } else if (EPI == 2) {
                bf16* dstb = Cb + (size_t)z * c_zs;
#pragma unroll
                for (int ni = 0; ni < 8; ni++)
#pragma unroll
                    for (int cc = 0; cc < 2; cc++) {
                        int col = bn + wn + ni * 8 + (lane & 3) * 2 + cc;
                        float g = gelu_f(c[mi][ni][rr * 2 + cc] + bias[col]);
                        bf16 hi = __float2bfloat16(g);
                        bf16 lo = __float2bfloat16(g - __bfloat162float(hi));
                        size_t base = (size_t)r * 2 * N;
                        dstb[base + col] = hi;
                        dstb[base + N + col] = lo;
                    }
            } else {
#pragma unroll
                for (int ni = 0; ni < 8; ni++)
#pragma unroll
                    for (int cc = 0; cc < 2; cc++) {
                        int col = bn + wn + ni * 8 + (lane & 3) * 2 + cc;
                        float val = c[mi][ni][rr * 2 + cc];
                        if (EPI == 0) Cf[(size_t)r * N + col] = val;
                        else          Cf[(size_t)r * N + col] = val + resid[(size_t)r * N + col];
                    }
            }
        }
    }
}

// ---------------- small fp32 GEMM (kI: N=64, wI: N=4) --------------------------
__global__ void __launch_bounds__(256, 2)
sgemm_small_kernel(const float* __restrict__ A, const float* __restrict__ B,
                   float* __restrict__ C, int M, int N, int K) {
    const int BM = 128, BN = 128, BK = 8, TM = 8, TN = 8;
    __shared__ float As[BK][BM];
    __shared__ float Bs[BK][BN];
    int tid = threadIdx.x;
    int bm = blockIdx.y * BM;
    int bn = blockIdx.x * BN;
    int trow = (tid / 16) * TM;
    int tcol = (tid % 16) * TN;
    float acc[TM][TN];
#pragma unroll
    for (int i = 0; i < TM; i++)
#pragma unroll
        for (int j = 0; j < TN; j++) acc[i][j] = 0.f;
    int arow = tid >> 1, acol = (tid & 1) * 4;
    int brow = tid >> 5, bcol = (tid & 31) * 4;
    const float* Aptr = A + (size_t)(bm + arow) * K;
    for (int k0 = 0; k0 < K; k0 += BK) {
        float4 av = *(const float4*)(Aptr + k0 + acol);
        As[acol + 0][arow] = av.x; As[acol + 1][arow] = av.y;
        As[acol + 2][arow] = av.z; As[acol + 3][arow] = av.w;
        int bc = bn + bcol;
#pragma unroll
        for (int j = 0; j < 4; j++)
            Bs[brow][bcol + j] = (bc + j < N) ? B[(size_t)(k0 + brow) * N + bc + j] : 0.f;
        __syncthreads();
#pragma unroll
        for (int kk = 0; kk < BK; kk++) {
            float ar[TM], br[TN];
#pragma unroll
            for (int i = 0; i < TM; i++) ar[i] = As[kk][trow + i];
#pragma unroll
            for (int j = 0; j < TN; j++) br[j] = Bs[kk][tcol + j];
#pragma unroll
            for (int i = 0; i < TM; i++)
#pragma unroll
                for (int j = 0; j < TN; j++) acc[i][j] += ar[i] * br[j];
        }
        __syncthreads();
    }
#pragma unroll
    for (int i = 0; i < TM; i++) {
        int r = bm + trow + i;
#pragma unroll
        for (int j = 0; j < TN; j++) {
            int cidx = bn + tcol + j;
            if (cidx < N) C[(size_t)r * N + cidx] = acc[i][j];
        }
    }
}

// ---------------- indexer scores ------------------------------------------------
__global__ void idxscore_kernel(const float* __restrict__ qI, const float* __restrict__ kI,
                                const float* __restrict__ wI, float* __restrict__ sc) {
    int b  = blockIdx.z;
    int t0 = blockIdx.y * 16;
    int s0 = blockIdx.x * 64;
    if (s0 > t0 + 15) return;
    __shared__ float qIs[16][257];
    __shared__ float kIs[64][65];
    __shared__ float wIs[16][4];
    int tx = threadIdx.x, ty = threadIdx.y;
    int tid = ty * 16 + tx;
    for (int idx = tid; idx < 16 * 256; idx += 256) {
        int r = idx >> 8, c = idx & 255;
        qIs[r][c] = qI[((size_t)(b * Sz + t0 + r)) * 256 + c];
    }
    for (int idx = tid; idx < 64 * 64; idx += 256) {
        int r = idx >> 6, c = idx & 63;
        kIs[r][c] = kI[((size_t)(b * Sz + s0 + r)) * 64 + c];
    }
    if (tid < 64) wIs[tid >> 2][tid & 3] = wI[((size_t)(b * Sz + (tid >> 2) + t0)) * 4 + (tid & 3)];
    __syncthreads();

    float acc4[4] = {0.f, 0.f, 0.f, 0.f};
#pragma unroll
    for (int h = 0; h < 4; h++) {
        float dot[4] = {0.f, 0.f, 0.f, 0.f};
#pragma unroll
        for (int d = 0; d < 64; d++) {
            float qv = qIs[ty][h * 64 + d];
            dot[0] += qv * kIs[tx +  0][d];
            dot[1] += qv * kIs[tx + 16][d];
            dot[2] += qv * kIs[tx + 32][d];
            dot[3] += qv * kIs[tx + 48][d];
        }
        float wv = wIs[ty][h];
#pragma unroll
        for (int j = 0; j < 4; j++) acc4[j] += wv * fmaxf(dot[j], 0.f);
    }
    int t = t0 + ty;
#pragma unroll
    for (int j = 0; j < 4; j++) {
        int s = s0 + tx + 16 * j;
        if (s <= t) sc[((size_t)(b * Sz + t)) * Sz + s] = acc4[j];
    }
}

// ---------------- top-k (512) per (b,t): radix select, jax tie-break -----------
__global__ void topk_kernel(const float* __restrict__ sc, int* __restrict__ selidx,
                            int* __restrict__ selcnt) {
    int bt = blockIdx.x;
    int t = bt & (Sz - 1);
    int n = t + 1;
    int tid = threadIdx.x;
    int* outp = selidx + (size_t)bt * TKz;
    if (n <= TKz) {
        for (int i = tid; i < n; i += 256) outp[i] = i;
        if (tid == 0) selcnt[bt] = n;
        return;
    }
    const float* row = sc + (size_t)bt * Sz;
    __shared__ unsigned keys[Sz];
    for (int i = tid; i < n; i += 256) {
        unsigned u = __float_as_uint(row[i]);
        keys[i] = (u & 0x80000000u) ? ~u : (u | 0x80000000u);
    }
    __shared__ int hist[256];
    __shared__ unsigned p_s;
    __shared__ int need_s;
    if (tid == 0) { p_s = 0; need_s = TKz; }
    __syncthreads();
    for (int byte = 3; byte >= 0; byte--) {
        int sh = byte * 8;
        for (int i = tid; i < 256; i += 256) hist[i] = 0;
        __syncthreads();
        unsigned p = p_s;
        unsigned mask_hi = (byte == 3) ? 0u : (0xFFFFFFFFu << (sh + 8));
        for (int i = tid; i < n; i += 256) {
            unsigned k = keys[i];
            if ((k & mask_hi) == p) atomicAdd(&hist[(k >> sh) & 255u], 1);
        }
        __syncthreads();
        if (tid == 0) {
            int need = need_s;
            int acc = 0;
            int chosen = 0;
            for (int b2 = 255; b2 >= 0; b2--) {
                if (acc + hist[b2] >= need) { chosen = b2; break; }
                acc += hist[b2];
            }
            need_s = need - acc;
            p_s = p | ((unsigned)chosen << sh);
        }
        __syncthreads();
    }
    unsigned p = p_s;   // exact TKz-th largest key
    __shared__ int pos;
    if (tid == 0) pos = 0;
    __syncthreads();
    for (int i = tid; i < n; i += 256)
        if (keys[i] > p) { int j = atomicAdd(&pos, 1); outp[j] = i; }
    __syncthreads();
    if (tid == 0) {
        int j = pos;
        for (int i = 0; i < n && j < TKz; i++)
            if (keys[i] == p) outp[j++] = i;
        selcnt[bt] = TKz;
    }
}

// ---------------- sparse attention (bf16 K/V), two-phase ------------------------
__global__ void __launch_bounds__(512)
attn_kernel(const float* __restrict__ q, const bf16* __restrict__ kb,
            const bf16* __restrict__ vb, const int* __restrict__ selidx,
            const int* __restrict__ selcnt, bf16* __restrict__ aox) {
    int bt = blockIdx.x;
    int b = bt >> 11;
    int tid = threadIdx.x;
    __shared__ float qs[Hz * DHz];
    __shared__ int sels[TKz + 4];
    __shared__ float sscore[Hz][TKz];
    int n = selcnt[bt];
    int n4 = (n + 3) & ~3;
    for (int i = tid; i < Dz; i += 512) qs[i] = q[(size_t)bt * Dz + i];
    for (int i = tid; i < n; i += 512) sels[i] = selidx[(size_t)bt * TKz + i];
    if (tid < 4) sels[n + tid] = selidx[(size_t)bt * TKz];   // pad with sel 0
    __syncthreads();
    int h = tid >> 5, lane = tid & 31;
    float q0 = qs[h * 64 + 2 * lane], q1 = qs[h * 64 + 2 * lane + 1];
    size_t hoff = h * 64 + 2 * lane;
    float m = -3.0e38f;
    // Phase A: all scores -> smem (4-way unrolled, overlapped shuffle chains)
    for (int i = 0; i < n4; i += 4) {
        float part[4];
#pragma unroll
        for (int j = 0; j < 4; j++) {
            int s = sels[i + j];
            float2 kf = __bfloat1622float2(
                *(const __nv_bfloat162*)(kb + ((size_t)(b * Sz + s)) * Dz + hoff));
            part[j] = q0 * kf.x + q1 * kf.y;
        }
#pragma unroll
        for (int off = 16; off; off >>= 1)
#pragma unroll
            for (int j = 0; j < 4; j++)
                part[j] += __shfl_xor_sync(0xffffffffu, part[j], off);
#pragma unroll
        for (int j = 0; j < 4; j++) {
            float scv = part[j] * 0.125f;
            sscore[h][i + j] = scv;
            m = fmaxf(m, scv);
        }
    }
    // Phase B: independent accumulation (MLP-friendly)
    float l = 0.f, o0 = 0.f, o1 = 0.f;
#pragma unroll 4
    for (int i = 0; i < n; i++) {
        float pw = __expf(sscore[h][i] - m);
        int s = sels[i];
        float2 vf = __bfloat1622float2(
            *(const __nv_bfloat162*)(vb + ((size_t)(b * Sz + s)) * Dz + hoff));
        o0 += pw * vf.x;
        o1 += pw * vf.y;
        l += pw;
    }
    float inv = 1.0f / l;
    o0 *= inv; o1 *= inv;
    size_t base = (size_t)bt * 2 * Dz;
    int c0 = h * 64 + 2 * lane, c1 = c0 + 1;
    bf16 h0 = __float2bfloat16(o0);
    bf16 l0 = __float2bfloat16(o0 - __bfloat162float(h0));
    bf16 h1 = __float2bfloat16(o1);
    bf16 l1 = __float2bfloat16(o1 - __bfloat162float(h1));
    aox[base + c0] = h0;       aox[base + c1] = h1;
    aox[base + Dz + c0] = l0;  aox[base + Dz + c1] = l1;
}

// ---------------- gate: softmax(4) + top-2 + combine weights -------------------
__global__ void gate_kernel(const float* __restrict__ xn2, const float* __restrict__ gw,
                            float* __restrict__ wdense, float* __restrict__ probsb) {
    int t = blockIdx.x;
    int tid = threadIdx.x;
    const float* xr = xn2 + (size_t)t * Dz;
    float le[4] = {0.f, 0.f, 0.f, 0.f};
    for (int d = tid; d < Dz; d += 256) {
        float xv = xr[d];
        const float* g = gw + (size_t)d * 4;
        le[0] += xv * g[0]; le[1] += xv * g[1];
        le[2] += xv * g[2]; le[3] += xv * g[3];
    }
    __shared__ float red[4][256];
    for (int e = 0; e < 4; e++) red[e][tid] = le[e];
    __syncthreads();
    for (int off = 128; off; off >>= 1) {
        if (tid < off)
            for (int e = 0; e < 4; e++) red[e][tid] += red[e][tid + off];
        __syncthreads();
    }
    if (tid == 0) {
        float lg[4], pr[4];
        float mx = -3.0e38f;
        for (int e = 0; e < 4; e++) { lg[e] = red[e][0]; mx = fmaxf(mx, lg[e]); }
        float sum = 0.f;
        for (int e = 0; e < 4; e++) { pr[e] = expf(lg[e] - mx); sum += pr[e]; }
        float inv = 1.0f / sum;
        for (int e = 0; e < 4; e++) { pr[e] *= inv; probsb[(size_t)t * 4 + e] = pr[e]; }
        int i1 = 0;
        for (int e = 1; e < 4; e++) if (pr[e] > pr[i1]) i1 = e;
        int i2 = -1; float b2v = -1.f;
        for (int e = 0; e < 4; e++) if (e != i1 && pr[e] > b2v) { b2v = pr[e]; i2 = e; }
        float wsum = pr[i1] + pr[i2];
        float wd[4] = {0.f, 0.f, 0.f, 0.f};
        wd[i1] = pr[i1] / wsum;
        wd[i2] = pr[i2] / wsum;
        for (int e = 0; e < 4; e++) wdense[(size_t)t * 4 + e] = wd[e];
    }
}

// ---------------- routing -------------------------------------------------------
__global__ void route_zero_kernel(int* __restrict__ ecnt) {
    if (threadIdx.x < Ez) ecnt[threadIdx.x] = 0;
}
__global__ void route_kernel(const float* __restrict__ wd, int* __restrict__ ecnt,
                             int* __restrict__ elist) {
    int t = blockIdx.x * blockDim.x + threadIdx.x;
    if (t < Tz) {
#pragma unroll
        for (int e = 0; e < Ez; e++)
            if (wd[(size_t)t * Ez + e] > 0.f) {
                int p = atomicAdd(&ecnt[e], 1);
                elist[e * Tz + p] = t;
            }
    }
}
__global__ void route_pad_kernel(const int* __restrict__ ecnt, int* __restrict__ elist) {
    int e = blockIdx.x;
    int cnt = ecnt[e];
    int padded = (cnt + 127) & ~127;
    for (int i = cnt + threadIdx.x; i < padded; i += blockDim.x) elist[e * Tz + i] = 0;
}

// ---------------- aux loss ------------------------------------------------------
__global__ void aux_kernel(const float* __restrict__ probsb, const float* __restrict__ wdense,
                           float* __restrict__ out_aux) {
    int tid = threadIdx.x;
    float sP[4] = {0.f, 0.f, 0.f, 0.f}, sF[4] = {0.f, 0.f, 0.f, 0.f};
    for (int t = tid; t < Tz; t += 256)
        for (int e = 0; e < 4; e++) {
            sP[e] += probsb[(size_t)t * 4 + e];
            sF[e] += (wdense[(size_t)t * 4 + e] > 0.f) ? 1.f : 0.f;
        }
    __shared__ float rP[4][256], rF[4][256];
    for (int e = 0; e < 4; e++) { rP[e][tid] = sP[e]; rF[e][tid] = sF[e]; }
    __syncthreads();
    for (int off = 128; off; off >>= 1) {
        if (tid < off)
            for (int e = 0; e < 4; e++) {
                rP[e][tid] += rP[e][tid + off];
                rF[e][tid] += rF[e][tid + off];
            }
        __syncthreads();
    }
    if (tid == 0) {
        float aux = 0.f;
        for (int e = 0; e < 4; e++)
            aux += (rF[e][0] * (1.0f / Tz)) * (rP[e][0] * (1.0f / Tz));
        *out_aux = (float)Ez * aux;
    }
}

// ---------------- final: out = x2 + sum_e masked ffe[e] -------------------------
__global__ void final_kernel(const float* __restrict__ x2, const float* __restrict__ ffe,
                             const float* __restrict__ wd, float* __restrict__ out) {
    for (int i = blockIdx.x * blockDim.x + threadIdx.x; i < Tz * Dz;
         i += gridDim.x * blockDim.x) {
        int t = i >> 10;
        float s = x2[i];
#pragma unroll
        for (int e = 0; e < Ez; e++)
            if (wd[(size_t)t * Ez + e] > 0.f) s += ffe[(size_t)e * Tz * Dz + i];
        out[i] = s;
    }
}

// ---------------- launch -------------------------------------------------------
extern "C" void kernel_launch(void* const* d_in, const int* in_sizes, int n_in,
                              void* d_out, int out_size) {
    const float* x      = (const float*)d_in[0];
    const float* n1w    = (const float*)d_in[1];
    const float* n2w    = (const float*)d_in[2];
    const float* wq     = (const float*)d_in[3];
    const float* wk     = (const float*)d_in[4];
    const float* wv     = (const float*)d_in[5];
    const float* wo     = (const float*)d_in[6];
    const float* idx_wq = (const float*)d_in[7];
    const float* idx_wk = (const float*)d_in[8];
    const float* idx_ww = (const float*)d_in[9];
    const float* gate_w = (const float*)d_in[10];
    const float* w1     = (const float*)d_in[11];
    const float* b1     = (const float*)d_in[12];
    const float* w2     = (const float*)d_in[13];
    const float* b2     = (const float*)d_in[14];
    float* out = (float*)d_out;

    float *xn, *q, *qI, *kI, *wI, *sc, *x2, *xn2, *wd, *pr, *ffe;
    int *selidx, *selcnt, *ecnt, *elist;
    bf16 *kvb, *xnx, *xn2x, *aox, *hx, *wqkvx, *wox, *iwqx, *w1x, *w2x;
    cudaGetSymbolAddress((void**)&xn,  g_xn);
    cudaGetSymbolAddress((void**)&q,   g_q);
    cudaGetSymbolAddress((void**)&qI,  g_qI);
    cudaGetSymbolAddress((void**)&kI,  g_kI);
    cudaGetSymbolAddress((void**)&wI,  g_wI);
    cudaGetSymbolAddress((void**)&sc,  g_sc);
    cudaGetSymbolAddress((void**)&selidx, g_selidx);
    cudaGetSymbolAddress((void**)&selcnt, g_selcnt);
    cudaGetSymbolAddress((void**)&x2,  g_x2);
    cudaGetSymbolAddress((void**)&xn2, g_xn2);
    cudaGetSymbolAddress((void**)&wd,  g_wd);
    cudaGetSymbolAddress((void**)&pr,  g_pr);
    cudaGetSymbolAddress((void**)&ffe, g_ffe);
    cudaGetSymbolAddress((void**)&ecnt,  g_ecnt);
    cudaGetSymbolAddress((void**)&elist, g_elist);
    cudaGetSymbolAddress((void**)&kvb,  g_kvb);
    cudaGetSymbolAddress((void**)&xnx,  g_xnx);
    cudaGetSymbolAddress((void**)&xn2x, g_xn2x);
    cudaGetSymbolAddress((void**)&aox,  g_aox);
    cudaGetSymbolAddress((void**)&hx,   g_hx);
    cudaGetSymbolAddress((void**)&wqkvx, g_wqkvx);
    cudaGetSymbolAddress((void**)&wox,  g_wox);
    cudaGetSymbolAddress((void**)&iwqx, g_iwqx);
    cudaGetSymbolAddress((void**)&w1x,  g_w1x);
    cudaGetSymbolAddress((void**)&w2x,  g_w2x);

    // dynamic smem opt-in for the 3-stage GEMM (idempotent)
    cudaFuncSetAttribute(hgemm_kernel<0>, cudaFuncAttributeMaxDynamicSharedMemorySize, HG_SMEM);
    cudaFuncSetAttribute(hgemm_kernel<1>, cudaFuncAttributeMaxDynamicSharedMemorySize, HG_SMEM);
    cudaFuncSetAttribute(hgemm_kernel<2>, cudaFuncAttributeMaxDynamicSharedMemorySize, HG_SMEM);
    cudaFuncSetAttribute(hgemm_kernel<3>, cudaFuncAttributeMaxDynamicSharedMemorySize, HG_SMEM);
    cudaFuncSetAttribute(hgemm_kernel<5>, cudaFuncAttributeMaxDynamicSharedMemorySize, HG_SMEM);

    const size_t WZ = (size_t)2 * Dz * Dz;

    // ---- weight split ([hi;lo]) ----
    convw_kernel<<<256, 256>>>(wq, wqkvx, Dz, 10);
    convw_kernel<<<256, 256>>>(wk, wqkvx + WZ, Dz, 10);
    convw_kernel<<<256, 256>>>(wv, wqkvx + 2 * WZ, Dz, 10);
    convw_kernel<<<256, 256>>>(wo, wox, Dz, 10);
    convw_kernel<<<64, 256>>>(idx_wq, iwqx, Dz, 8);
    for (int e = 0; e < Ez; e++) {
        convw_kernel<<<1024, 256>>>(w1 + (size_t)e * Dz * DFz,
                                    w1x + (size_t)e * 2 * Dz * DFz, Dz, 12);
        convw_kernel<<<1024, 256>>>(w2 + (size_t)e * DFz * Dz,
                                    w2x + (size_t)e * 2 * DFz * Dz, DFz, 10);
    }

    // ---- attention path ----
    rmsnorm2_kernel<<<Tz, 256>>>(x, n1w, xn, xnx);
    hgemm_kernel<5><<<dim3(8, 32, 3), 128, HG_SMEM>>>(xnx, wqkvx, q, kvb, Tz, Dz, Dz,
                                             nullptr, nullptr, nullptr, nullptr, nullptr,
                                             0, WZ, (size_t)Tz * Dz, 0);
    hgemm_kernel<0><<<dim3(2, 32), 128, HG_SMEM>>>(xnx, iwqx, qI, nullptr, Tz, HIz * DIz, Dz,
                                          nullptr, nullptr, nullptr, nullptr, nullptr,
                                          0, 0, 0, 0);
    sgemm_small_kernel<<<dim3(1, 32), 256>>>(xn, idx_wk, kI, Tz, DIz, Dz);
    sgemm_small_kernel<<<dim3(1, 32), 256>>>(xn, idx_ww, wI, Tz, HIz, Dz);

    idxscore_kernel<<<dim3(Sz / 64, Sz / 16, Bz), dim3(16, 16)>>>(qI, kI, wI, sc);
    topk_kernel<<<Tz, 256>>>(sc, selidx, selcnt);
    attn_kernel<<<Tz, 512>>>(q, kvb, kvb + (size_t)Tz * Dz, selidx, selcnt, aox);
    hgemm_kernel<1><<<dim3(8, 32), 128, HG_SMEM>>>(aox, wox, x2, nullptr, Tz, Dz, Dz,
                                          nullptr, x, nullptr, nullptr, nullptr,
                                          0, 0, 0, 0);

    // ---- MoE path (routed + expert-batched) ----
    rmsnorm2_kernel<<<Tz, 256>>>(x2, n2w, xn2, xn2x);
    gate_kernel<<<Tz, 256>>>(xn2, gate_w, wd, pr);
    route_zero_kernel<<<1, 32>>>(ecnt);
    route_kernel<<<Tz / 256, 256>>>(wd, ecnt, elist);
    route_pad_kernel<<<Ez, 128>>>(ecnt, elist);
    hgemm_kernel<2><<<dim3(32, 32, Ez), 128, HG_SMEM>>>(xn2x, w1x, nullptr, hx, Tz, DFz, Dz,
                                               b1, nullptr, nullptr, elist, ecnt,
                                               0, (size_t)2 * Dz * DFz,
                                               (size_t)Tz * 2 * DFz, DFz);
    hgemm_kernel<3><<<dim3(8, 32, Ez), 128, HG_SMEM>>>(hx, w2x, ffe, nullptr, Tz, Dz, DFz,
                                              b2, nullptr, wd, elist, ecnt,
                                              (size_t)Tz * 2 * DFz, (size_t)2 * DFz * Dz,
                                              (size_t)Tz * Dz, Dz);

    final_kernel<<<8192, 256>>>(x2, ffe, wd, out);
    aux_kernel<<<1, 256>>>(pr, wd, out + (out_size - 1));
}

// round 15
// speedup vs baseline: 1.6022x; 1.6022x over previous
#include <cuda_runtime.h>
#include <cuda_bf16.h>
#include <math.h>
#include <stdint.h>

// Problem dims (fixed by setup_inputs)
#define Bz 2
#define Sz 2048
#define Dz 1024
#define Tz 4096           // B*S
#define Hz 16
#define DHz 64
#define HIz 4
#define DIz 64
#define TKz 512
#define Ez 4
#define DFz 4096

typedef __nv_bfloat16 bf16;

// ---------------- scratch (device globals; no allocation allowed) --------------
__device__ float g_xn [Tz*Dz];
__device__ float g_q  [Tz*Dz];
__device__ float g_qI [Tz*HIz*DIz];
__device__ float g_kI [Tz*DIz];
__device__ float g_wI [Tz*HIz];
__device__ float g_sc [(size_t)Bz*Sz*Sz];
__device__ int   g_selidx[(size_t)Tz*TKz];
__device__ int   g_selcnt[Tz];
__device__ float g_x2 [Tz*Dz];
__device__ float g_xn2[Tz*Dz];
__device__ float g_wd [Tz*Ez];
__device__ float g_pr [Tz*Ez];
__device__ int   g_ecnt[Ez];
__device__ int   g_elist[Ez*Tz];
__device__ float g_ffe[(size_t)Ez*Tz*Dz];

// bf16 operands: split storage is [hi|lo] (2K); GEMM remaps k-blocks to get
// the 3-term product Ahi*Bhi + Ahi*Blo + Alo*Bhi.
__device__ bf16 g_kvb  [(size_t)2*Tz*Dz];
__device__ bf16 g_xnx  [(size_t)Tz*2*Dz];
__device__ bf16 g_xn2x [(size_t)Tz*2*Dz];
__device__ bf16 g_aox  [(size_t)Tz*2*Dz];
__device__ bf16 g_hx   [(size_t)Ez*Tz*2*DFz];
__device__ bf16 g_wqkvx[(size_t)3*2*Dz*Dz];
__device__ bf16 g_wox  [2*Dz*Dz];
__device__ bf16 g_iwqx [2*Dz*HIz*DIz];
__device__ bf16 g_w1x  [(size_t)Ez*2*Dz*DFz];
__device__ bf16 g_w2x  [(size_t)Ez*2*DFz*Dz];

// ---------------- helpers ------------------------------------------------------
__device__ __forceinline__ float gelu_f(float x) {
    float x3 = x * x * x;
    return 0.5f * x * (1.0f + tanhf(0.7978845608028654f * (x + 0.044715f * x3)));
}
__device__ __forceinline__ uint32_t smem_u32(const void* p) {
    return (uint32_t)__cvta_generic_to_shared(p);
}
__device__ __forceinline__ void ldsm4(uint32_t& r0, uint32_t& r1, uint32_t& r2,
                                      uint32_t& r3, uint32_t a) {
    asm volatile("ldmatrix.sync.aligned.m8n8.x4.shared.b16 {%0,%1,%2,%3}, [%4];\n"
                 : "=r"(r0), "=r"(r1), "=r"(r2), "=r"(r3) : "r"(a));
}
__device__ __forceinline__ void ldsm4t(uint32_t& r0, uint32_t& r1, uint32_t& r2,
                                       uint32_t& r3, uint32_t a) {
    asm volatile("ldmatrix.sync.aligned.m8n8.x4.trans.shared.b16 {%0,%1,%2,%3}, [%4];\n"
                 : "=r"(r0), "=r"(r1), "=r"(r2), "=r"(r3) : "r"(a));
}
__device__ __forceinline__ void mma_bf16(float c[4], uint32_t a0, uint32_t a1,
                                         uint32_t a2, uint32_t a3,
                                         uint32_t b0, uint32_t b1) {
    asm volatile("mma.sync.aligned.m16n8k16.row.col.f32.bf16.bf16.f32 "
                 "{%0,%1,%2,%3}, {%4,%5,%6,%7}, {%8,%9}, {%0,%1,%2,%3};\n"
                 : "+f"(c[0]), "+f"(c[1]), "+f"(c[2]), "+f"(c[3])
                 : "r"(a0), "r"(a1), "r"(a2), "r"(a3), "r"(b0), "r"(b1));
}
#define CPA16(dst, src) \
    asm volatile("cp.async.cg.shared.global [%0], [%1], 16;\n" :: "r"(dst), "l"(src))
#define CPA_COMMIT() asm volatile("cp.async.commit_group;\n" ::)
#define CPA_WAIT0()  asm volatile("cp.async.wait_group 0;\n" ::)

// ---------------- rmsnorm (fp32 out optional + bf16 [hi|lo] out) ---------------
__global__ void rmsnorm2_kernel(const float* __restrict__ x, const float* __restrict__ w,
                                float* __restrict__ y, bf16* __restrict__ yx) {
    int t = blockIdx.x;
    int tid = threadIdx.x;
    const float* xr = x + (size_t)t * Dz;
    float s = 0.f;
    for (int i = tid; i < Dz; i += 256) { float v = xr[i]; s += v * v; }
    __shared__ float red[256];
    red[tid] = s; __syncthreads();
    for (int off = 128; off; off >>= 1) {
        if (tid < off) red[tid] += red[tid + off];
        __syncthreads();
    }
    float inv = rsqrtf(red[0] * (1.0f / Dz) + 1e-6f);
    bf16* yr = yx + (size_t)t * 2 * Dz;
    for (int i = tid; i < Dz; i += 256) {
        float v = xr[i] * inv * w[i];
        if (y) y[(size_t)t * Dz + i] = v;
        bf16 hi = __float2bfloat16(v);
        bf16 lo = __float2bfloat16(v - __bfloat162float(hi));
        yr[i] = hi;
        yr[Dz + i] = lo;
    }
}

// ---------------- weight split: [K][N] fp32 -> [2K][N] bf16 [hi;lo] ------------
// N power of two (logN >= 3). Each iteration: 2 independent float4 loads (MLP=2),
// one 16B store per stream.
__global__ void convw_kernel(const float* __restrict__ src, bf16* __restrict__ dst,
                             int K, int logN) {
    unsigned nmask = (unsigned)((1 << logN) - 1);
    size_t total8 = ((size_t)K << logN) >> 3;
    for (size_t g = blockIdx.x * blockDim.x + threadIdx.x; g < total8;
         g += (size_t)gridDim.x * blockDim.x) {
        float4 a0 = ((const float4*)src)[g * 2];
        float4 a1 = ((const float4*)src)[g * 2 + 1];
        __align__(16) bf16 hv[8], lv[8];
        const float* f0 = (const float*)&a0;
        const float* f1 = (const float*)&a1;
#pragma unroll
        for (int q = 0; q < 4; q++) {
            bf16 hi = __float2bfloat16(f0[q]);
            hv[q] = hi;
            lv[q] = __float2bfloat16(f0[q] - __bfloat162float(hi));
        }
#pragma unroll
        for (int q = 0; q < 4; q++) {
            bf16 hi = __float2bfloat16(f1[q]);
            hv[4 + q] = hi;
            lv[4 + q] = __float2bfloat16(f1[q] - __bfloat162float(hi));
        }
        size_t base = g << 3;
        int k = (int)(base >> logN);
        int n = (int)(base & nmask);
        *(float4*)&dst[((size_t)k << logN) + n] = *(float4*)hv;
        *(float4*)&dst[((size_t)(K + k) << logN) + n] = *(float4*)lv;
    }
}

// ---------------- bf16 tensor-core GEMM (z-batched, 3-term remap) ---------------
// Logical C[M,N] = A[M,3*Kthird] x B[3*Kthird,N] stored [hi|lo] (2*Kthird);
// k-block kt maps: A-block = kt<KB?kt:kt-KB, B-block = kt<2KB?kt:kt-2KB.
// 128 threads, 4 warps, warp tile 64x64, CTA tile 128x128.
// EPI 0: Cf = val
// EPI 1: Cf = val + resid
// EPI 2: gather A rows via elist[z]; Cb+z*c_zs [hi|lo] (stride 2N) of gelu(val+bias)
// EPI 3: scatter: (Cf+z*c_zs)[tok*N+c] = wdv[tok*Ez+z]*(val+bias[c])
// EPI 5: QKV: z==0 -> Cf fp32; z>=1 -> (Cb+(z-1)*c_zs) plain bf16
template<int EPI>
__global__ void __launch_bounds__(128, 2)
hgemm_kernel(const bf16* __restrict__ A, const bf16* __restrict__ B,
             float* __restrict__ Cf, bf16* __restrict__ Cb,
             int M, int N, int Kthird,
             const float* __restrict__ bias, const float* __restrict__ resid,
             const float* __restrict__ wdv,
             const int* __restrict__ elist, const int* __restrict__ ecnt,
             size_t a_zs, size_t b_zs, size_t c_zs, int bias_zs) {
    int z = blockIdx.z;
    int bm = blockIdx.y * 128, bn = blockIdx.x * 128;
    int cnt = M;
    if (ecnt) {
        cnt = ecnt[z];
        int padded = (cnt + 127) & ~127;
        if (bm >= padded) return;
    }
    A += (size_t)z * a_zs;
    B += (size_t)z * b_zs;
    if (bias) bias += (size_t)z * bias_zs;
    const int* lst = elist ? elist + (size_t)z * Tz : nullptr;

    __shared__ __align__(16) bf16 As[2][128][40];
    __shared__ __align__(16) bf16 Bs[2][32][136];
    int tid = threadIdx.x;
    int warp = tid >> 5, lane = tid & 31;
    int wm = (warp & 1) * 64, wn = (warp >> 1) * 64;

    const int KB = Kthird >> 5;
    const int KT = 3 * KB;
    const int AS = 2 * Kthird;

    int arow = tid >> 2, acol = (tid & 3) * 8;
    int brow = tid >> 4, bcol = (tid & 15) * 8;
    const bf16* Ag[4];
#pragma unroll
    for (int j = 0; j < 4; j++) {
        int r = bm + arow + 32 * j;
        if (EPI == 2) r = lst[r];
        Ag[j] = A + (size_t)r * AS + acol;
    }
    const bf16* Bg = B + (size_t)brow * N + bn + bcol;

    float c[4][8][4];
#pragma unroll
    for (int mi = 0; mi < 4; mi++)
#pragma unroll
        for (int ni = 0; ni < 8; ni++)
#pragma unroll
            for (int j = 0; j < 4; j++) c[mi][ni][j] = 0.f;

    {
#pragma unroll
        for (int j = 0; j < 4; j++)
            CPA16(smem_u32(&As[0][arow + 32 * j][acol]), Ag[j]);
#pragma unroll
        for (int j = 0; j < 4; j++)
            CPA16(smem_u32(&Bs[0][brow + 8 * j][bcol]), Bg + (size_t)(8 * j) * N);
        CPA_COMMIT();
    }
    int buf = 0;
    for (int kt = 0; kt < KT; kt++) {
        CPA_WAIT0();
        __syncthreads();
        if (kt + 1 < KT) {
            int nb = buf ^ 1;
            int k2 = kt + 1;
            int ak = (k2 < KB) ? k2 : k2 - KB;
            int bk = (k2 < 2 * KB) ? k2 : k2 - 2 * KB;
#pragma unroll
            for (int j = 0; j < 4; j++)
                CPA16(smem_u32(&As[nb][arow + 32 * j][acol]), Ag[j] + ak * 32);
#pragma unroll
            for (int j = 0; j < 4; j++)
                CPA16(smem_u32(&Bs[nb][brow + 8 * j][bcol]),
                      Bg + (size_t)(bk * 32 + 8 * j) * N);
            CPA_COMMIT();
        }
#pragma unroll
        for (int kk = 0; kk < 32; kk += 16) {
            uint32_t a[4][4], b[8][2];
#pragma unroll
            for (int mi = 0; mi < 4; mi++) {
                uint32_t addr = smem_u32(
                    &As[buf][wm + mi * 16 + (lane & 15)][kk + ((lane >> 4) << 3)]);
                ldsm4(a[mi][0], a[mi][1], a[mi][2], a[mi][3], addr);
            }
#pragma unroll
            for (int nj = 0; nj < 4; nj++) {
                uint32_t addr = smem_u32(
                    &Bs[buf][kk + (lane & 15)][wn + nj * 16 + ((lane >> 4) << 3)]);
                ldsm4t(b[2 * nj][0], b[2 * nj][1], b[2 * nj + 1][0], b[2 * nj + 1][1], addr);
            }
#pragma unroll
            for (int mi = 0; mi < 4; mi++)
#pragma unroll
                for (int ni = 0; ni < 8; ni++)
                    mma_bf16(c[mi][ni], a[mi][0], a[mi][1], a[mi][2], a[mi][3],
                             b[ni][0], b[ni][1]);
        }
        buf ^= 1;
    }

#pragma unroll
    for (int mi = 0; mi < 4; mi++) {
#pragma unroll
        for (int rr = 0; rr < 2; rr++) {
            int r = bm + wm + mi * 16 + (lane >> 2) + rr * 8;
            if (EPI == 3) {
                if (r < cnt) {
                    int tok = lst[r];
                    float rsc = wdv[(size_t)tok * Ez + z];
                    float* dst = Cf + (size_t)z * c_zs;
#pragma unroll
                    for (int ni = 0; ni < 8; ni++)
#pragma unroll
                        for (int cc = 0; cc < 2; cc++) {
                            int col = bn + wn + ni * 8 + (lane & 3) * 2 + cc;
                            dst[(size_t)tok * N + col] =
                                rsc * (c[mi][ni][rr * 2 + cc] + bias[col]);
                        }
                }
            } else if (EPI == 5) {
                if (z == 0) {
#pragma unroll
                    for (int ni = 0; ni < 8; ni++)
#pragma unroll
                        for (int cc = 0; cc < 2; cc++) {
                            int col = bn + wn + ni * 8 + (lane & 3) * 2 + cc;
                            Cf[(size_t)r * N + col] = c[mi][ni][rr * 2 + cc];
                        }
                } else {
                    bf16* dst = Cb + (size_t)(z - 1) * c_zs;
#pragma unroll
                    for (int ni = 0; ni < 8; ni++) {
                        int colb = bn + wn + ni * 8 + (lane & 3) * 2;
                        __nv_bfloat162 p;
                        p.x = __float2bfloat16(c[mi][ni][rr * 2]);
                        p.y = __float2bfloat16(c[mi][ni][rr * 2 + 1]);
                        *(__nv_bfloat162*)&dst[(size_t)r * N + colb] = p;
                    }
                }
            } else if (EPI == 2) {
                bf16* dstb = Cb + (size_t)z * c_zs;
#pragma unroll
                for (int ni = 0; ni < 8; ni++)
#pragma unroll
                    for (int cc = 0; cc < 2; cc++) {
                        int col = bn + wn + ni * 8 + (lane & 3) * 2 + cc;
                        float g = gelu_f(c[mi][ni][rr * 2 + cc] + bias[col]);
                        bf16 hi = __float2bfloat16(g);
                        bf16 lo = __float2bfloat16(g - __bfloat162float(hi));
                        size_t base = (size_t)r * 2 * N;
                        dstb[base + col] = hi;
                        dstb[base + N + col] = lo;
                    }
            } else {
#pragma unroll
                for (int ni = 0; ni < 8; ni++)
#pragma unroll
                    for (int cc = 0; cc < 2; cc++) {
                        int col = bn + wn + ni * 8 + (lane & 3) * 2 + cc;
                        float val = c[mi][ni][rr * 2 + cc];
                        if (EPI == 0) Cf[(size_t)r * N + col] = val;
                        else          Cf[(size_t)r * N + col] = val + resid[(size_t)r * N + col];
                    }
            }
        }
    }
}

// ---------------- small fp32 GEMM (kI: N=64, wI: N=4) --------------------------
__global__ void __launch_bounds__(256, 2)
sgemm_small_kernel(const float* __restrict__ A, const float* __restrict__ B,
                   float* __restrict__ C, int M, int N, int K) {
    const int BM = 128, BN = 128, BK = 8, TM = 8, TN = 8;
    __shared__ float As[BK][BM];
    __shared__ float Bs[BK][BN];
    int tid = threadIdx.x;
    int bm = blockIdx.y * BM;
    int bn = blockIdx.x * BN;
    int trow = (tid / 16) * TM;
    int tcol = (tid % 16) * TN;
    float acc[TM][TN];
#pragma unroll
    for (int i = 0; i < TM; i++)
#pragma unroll
        for (int j = 0; j < TN; j++) acc[i][j] = 0.f;
    int arow = tid >> 1, acol = (tid & 1) * 4;
    int brow = tid >> 5, bcol = (tid & 31) * 4;
    const float* Aptr = A + (size_t)(bm + arow) * K;
    for (int k0 = 0; k0 < K; k0 += BK) {
        float4 av = *(const float4*)(Aptr + k0 + acol);
        As[acol + 0][arow] = av.x; As[acol + 1][arow] = av.y;
        As[acol + 2][arow] = av.z; As[acol + 3][arow] = av.w;
        int bc = bn + bcol;
#pragma unroll
        for (int j = 0; j < 4; j++)
            Bs[brow][bcol + j] = (bc + j < N) ? B[(size_t)(k0 + brow) * N + bc + j] : 0.f;
        __syncthreads();
#pragma unroll
        for (int kk = 0; kk < BK; kk++) {
            float ar[TM], br[TN];
#pragma unroll
            for (int i = 0; i < TM; i++) ar[i] = As[kk][trow + i];
#pragma unroll
            for (int j = 0; j < TN; j++) br[j] = Bs[kk][tcol + j];
#pragma unroll
            for (int i = 0; i < TM; i++)
#pragma unroll
                for (int j = 0; j < TN; j++) acc[i][j] += ar[i] * br[j];
        }
        __syncthreads();
    }
#pragma unroll
    for (int i = 0; i < TM; i++) {
        int r = bm + trow + i;
#pragma unroll
        for (int j = 0; j < TN; j++) {
            int cidx = bn + tcol + j;
            if (cidx < N) C[(size_t)r * N + cidx] = acc[i][j];
        }
    }
}

// ---------------- indexer scores ------------------------------------------------
__global__ void idxscore_kernel(const float* __restrict__ qI, const float* __restrict__ kI,
                                const float* __restrict__ wI, float* __restrict__ sc) {
    int b  = blockIdx.z;
    int t0 = blockIdx.y * 16;
    int s0 = blockIdx.x * 64;
    if (s0 > t0 + 15) return;
    __shared__ float qIs[16][257];
    __shared__ float kIs[64][65];
    __shared__ float wIs[16][4];
    int tx = threadIdx.x, ty = threadIdx.y;
    int tid = ty * 16 + tx;
    for (int idx = tid; idx < 16 * 256; idx += 256) {
        int r = idx >> 8, c = idx & 255;
        qIs[r][c] = qI[((size_t)(b * Sz + t0 + r)) * 256 + c];
    }
    for (int idx = tid; idx < 64 * 64; idx += 256) {
        int r = idx >> 6, c = idx & 63;
        kIs[r][c] = kI[((size_t)(b * Sz + s0 + r)) * 64 + c];
    }
    if (tid < 64) wIs[tid >> 2][tid & 3] = wI[((size_t)(b * Sz + (tid >> 2) + t0)) * 4 + (tid & 3)];
    __syncthreads();

    float acc4[4] = {0.f, 0.f, 0.f, 0.f};
#pragma unroll
    for (int h = 0; h < 4; h++) {
        float dot[4] = {0.f, 0.f, 0.f, 0.f};
#pragma unroll
        for (int d = 0; d < 64; d++) {
            float qv = qIs[ty][h * 64 + d];
            dot[0] += qv * kIs[tx +  0][d];
            dot[1] += qv * kIs[tx + 16][d];
            dot[2] += qv * kIs[tx + 32][d];
            dot[3] += qv * kIs[tx + 48][d];
        }
        float wv = wIs[ty][h];
#pragma unroll
        for (int j = 0; j < 4; j++) acc4[j] += wv * fmaxf(dot[j], 0.f);
    }
    int t = t0 + ty;
#pragma unroll
    for (int j = 0; j < 4; j++) {
        int s = s0 + tx + 16 * j;
        if (s <= t) sc[((size_t)(b * Sz + t)) * Sz + s] = acc4[j];
    }
}

// ---------------- top-k (512) per (b,t): radix select, jax tie-break -----------
__global__ void topk_kernel(const float* __restrict__ sc, int* __restrict__ selidx,
                            int* __restrict__ selcnt) {
    int bt = blockIdx.x;
    int t = bt & (Sz - 1);
    int n = t + 1;
    int tid = threadIdx.x;
    int* outp = selidx + (size_t)bt * TKz;
    if (n <= TKz) {
        for (int i = tid; i < n; i += 256) outp[i] = i;
        if (tid == 0) selcnt[bt] = n;
        return;
    }
    const float* row = sc + (size_t)bt * Sz;
    __shared__ unsigned keys[Sz];
    for (int i = tid; i < n; i += 256) {
        unsigned u = __float_as_uint(row[i]);
        keys[i] = (u & 0x80000000u) ? ~u : (u | 0x80000000u);
    }
    __shared__ int hist[256];
    __shared__ unsigned p_s;
    __shared__ int need_s;
    if (tid == 0) { p_s = 0; need_s = TKz; }
    __syncthreads();
    for (int byte = 3; byte >= 0; byte--) {
        int sh = byte * 8;
        for (int i = tid; i < 256; i += 256) hist[i] = 0;
        __syncthreads();
        unsigned p = p_s;
        unsigned mask_hi = (byte == 3) ? 0u : (0xFFFFFFFFu << (sh + 8));
        for (int i = tid; i < n; i += 256) {
            unsigned k = keys[i];
            if ((k & mask_hi) == p) atomicAdd(&hist[(k >> sh) & 255u], 1);
        }
        __syncthreads();
        if (tid == 0) {
            int need = need_s;
            int acc = 0;
            int chosen = 0;
            for (int b2 = 255; b2 >= 0; b2--) {
                if (acc + hist[b2] >= need) { chosen = b2; break; }
                acc += hist[b2];
            }
            need_s = need - acc;
            p_s = p | ((unsigned)chosen << sh);
        }
        __syncthreads();
    }
    unsigned p = p_s;   // exact TKz-th largest key
    __shared__ int pos;
    if (tid == 0) pos = 0;
    __syncthreads();
    for (int i = tid; i < n; i += 256)
        if (keys[i] > p) { int j = atomicAdd(&pos, 1); outp[j] = i; }
    __syncthreads();
    if (tid == 0) {
        int j = pos;
        for (int i = 0; i < n && j < TKz; i++)
            if (keys[i] == p) outp[j++] = i;
        selcnt[bt] = TKz;
    }
}

// ---------------- sparse attention (bf16 K/V), two-phase ------------------------
__global__ void __launch_bounds__(512)
attn_kernel(const float* __restrict__ q, const bf16* __restrict__ kb,
            const bf16* __restrict__ vb, const int* __restrict__ selidx,
            const int* __restrict__ selcnt, bf16* __restrict__ aox) {
    int bt = blockIdx.x;
    int b = bt >> 11;
    int tid = threadIdx.x;
    __shared__ float qs[Hz * DHz];
    __shared__ int sels[TKz + 4];
    __shared__ float sscore[Hz][TKz];
    int n = selcnt[bt];
    int n4 = (n + 3) & ~3;
    for (int i = tid; i < Dz; i += 512) qs[i] = q[(size_t)bt * Dz + i];
    for (int i = tid; i < n; i += 512) sels[i] = selidx[(size_t)bt * TKz + i];
    if (tid < 4) sels[n + tid] = selidx[(size_t)bt * TKz];   // pad with sel 0
    __syncthreads();
    int h = tid >> 5, lane = tid & 31;
    float q0 = qs[h * 64 + 2 * lane], q1 = qs[h * 64 + 2 * lane + 1];
    size_t hoff = h * 64 + 2 * lane;
    float m = -3.0e38f;
    // Phase A: all scores -> smem (4-way unrolled, overlapped shuffle chains)
    for (int i = 0; i < n4; i += 4) {
        float part[4];
#pragma unroll
        for (int j = 0; j < 4; j++) {
            int s = sels[i + j];
            float2 kf = __bfloat1622float2(
                *(const __nv_bfloat162*)(kb + ((size_t)(b * Sz + s)) * Dz + hoff));
            part[j] = q0 * kf.x + q1 * kf.y;
        }
#pragma unroll
        for (int off = 16; off; off >>= 1)
#pragma unroll
            for (int j = 0; j < 4; j++)
                part[j] += __shfl_xor_sync(0xffffffffu, part[j], off);
#pragma unroll
        for (int j = 0; j < 4; j++) {
            float scv = part[j] * 0.125f;
            sscore[h][i + j] = scv;
            m = fmaxf(m, scv);
        }
    }
    // Phase B: independent accumulation (MLP-friendly)
    float l = 0.f, o0 = 0.f, o1 = 0.f;
#pragma unroll 4
    for (int i = 0; i < n; i++) {
        float pw = __expf(sscore[h][i] - m);
        int s = sels[i];
        float2 vf = __bfloat1622float2(
            *(const __nv_bfloat162*)(vb + ((size_t)(b * Sz + s)) * Dz + hoff));
        o0 += pw * vf.x;
        o1 += pw * vf.y;
        l += pw;
    }
    float inv = 1.0f / l;
    o0 *= inv; o1 *= inv;
    size_t base = (size_t)bt * 2 * Dz;
    int c0 = h * 64 + 2 * lane, c1 = c0 + 1;
    bf16 h0 = __float2bfloat16(o0);
    bf16 l0 = __float2bfloat16(o0 - __bfloat162float(h0));
    bf16 h1 = __float2bfloat16(o1);
    bf16 l1 = __float2bfloat16(o1 - __bfloat162float(h1));
    aox[base + c0] = h0;       aox[base + c1] = h1;
    aox[base + Dz + c0] = l0;  aox[base + Dz + c1] = l1;
}

// ---------------- gate: softmax(4) + top-2 + combine weights -------------------
__global__ void gate_kernel(const float* __restrict__ xn2, const float* __restrict__ gw,
                            float* __restrict__ wdense, float* __restrict__ probsb) {
    int t = blockIdx.x;
    int tid = threadIdx.x;
    const float* xr = xn2 + (size_t)t * Dz;
    float le[4] = {0.f, 0.f, 0.f, 0.f};
    for (int d = tid; d < Dz; d += 256) {
        float xv = xr[d];
        const float* g = gw + (size_t)d * 4;
        le[0] += xv * g[0]; le[1] += xv * g[1];
        le[2] += xv * g[2]; le[3] += xv * g[3];
    }
    __shared__ float red[4][256];
    for (int e = 0; e < 4; e++) red[e][tid] = le[e];
    __syncthreads();
    for (int off = 128; off; off >>= 1) {
        if (tid < off)
            for (int e = 0; e < 4; e++) red[e][tid] += red[e][tid + off];
        __syncthreads();
    }
    if (tid == 0) {
        float lg[4], pr[4];
        float mx = -3.0e38f;
        for (int e = 0; e < 4; e++) { lg[e] = red[e][0]; mx = fmaxf(mx, lg[e]); }
        float sum = 0.f;
        for (int e = 0; e < 4; e++) { pr[e] = expf(lg[e] - mx); sum += pr[e]; }
        float inv = 1.0f / sum;
        for (int e = 0; e < 4; e++) { pr[e] *= inv; probsb[(size_t)t * 4 + e] = pr[e]; }
        int i1 = 0;
        for (int e = 1; e < 4; e++) if (pr[e] > pr[i1]) i1 = e;
        int i2 = -1; float b2v = -1.f;
        for (int e = 0; e < 4; e++) if (e != i1 && pr[e] > b2v) { b2v = pr[e]; i2 = e; }
        float wsum = pr[i1] + pr[i2];
        float wd[4] = {0.f, 0.f, 0.f, 0.f};
        wd[i1] = pr[i1] / wsum;
        wd[i2] = pr[i2] / wsum;
        for (int e = 0; e < 4; e++) wdense[(size_t)t * 4 + e] = wd[e];
    }
}

// ---------------- routing -------------------------------------------------------
__global__ void route_zero_kernel(int* __restrict__ ecnt) {
    if (threadIdx.x < Ez) ecnt[threadIdx.x] = 0;
}
__global__ void route_kernel(const float* __restrict__ wd, int* __restrict__ ecnt,
                             int* __restrict__ elist) {
    int t = blockIdx.x * blockDim.x + threadIdx.x;
    if (t < Tz) {
#pragma unroll
        for (int e = 0; e < Ez; e++)
            if (wd[(size_t)t * Ez + e] > 0.f) {
                int p = atomicAdd(&ecnt[e], 1);
                elist[e * Tz + p] = t;
            }
    }
}
__global__ void route_pad_kernel(const int* __restrict__ ecnt, int* __restrict__ elist) {
    int e = blockIdx.x;
    int cnt = ecnt[e];
    int padded = (cnt + 127) & ~127;
    for (int i = cnt + threadIdx.x; i < padded; i += blockDim.x) elist[e * Tz + i] = 0;
}

// ---------------- aux loss ------------------------------------------------------
__global__ void aux_kernel(const float* __restrict__ probsb, const float* __restrict__ wdense,
                           float* __restrict__ out_aux) {
    int tid = threadIdx.x;
    float sP[4] = {0.f, 0.f, 0.f, 0.f}, sF[4] = {0.f, 0.f, 0.f, 0.f};
    for (int t = tid; t < Tz; t += 256)
        for (int e = 0; e < 4; e++) {
            sP[e] += probsb[(size_t)t * 4 + e];
            sF[e] += (wdense[(size_t)t * 4 + e] > 0.f) ? 1.f : 0.f;
        }
    __shared__ float rP[4][256], rF[4][256];
    for (int e = 0; e < 4; e++) { rP[e][tid] = sP[e]; rF[e][tid] = sF[e]; }
    __syncthreads();
    for (int off = 128; off; off >>= 1) {
        if (tid < off)
            for (int e = 0; e < 4; e++) {
                rP[e][tid] += rP[e][tid + off];
                rF[e][tid] += rF[e][tid + off];
            }
        __syncthreads();
    }
    if (tid == 0) {
        float aux = 0.f;
        for (int e = 0; e < 4; e++)
            aux += (rF[e][0] * (1.0f / Tz)) * (rP[e][0] * (1.0f / Tz));
        *out_aux = (float)Ez * aux;
    }
}

// ---------------- final: out = x2 + sum_e masked ffe[e] -------------------------
__global__ void final_kernel(const float* __restrict__ x2, const float* __restrict__ ffe,
                             const float* __restrict__ wd, float* __restrict__ out) {
    for (int i = blockIdx.x * blockDim.x + threadIdx.x; i < Tz * Dz;
         i += gridDim.x * blockDim.x) {
        int t = i >> 10;
        float s = x2[i];
#pragma unroll
        for (int e = 0; e < Ez; e++)
            if (wd[(size_t)t * Ez + e] > 0.f) s += ffe[(size_t)e * Tz * Dz + i];
        out[i] = s;
    }
}

// ---------------- launch -------------------------------------------------------
extern "C" void kernel_launch(void* const* d_in, const int* in_sizes, int n_in,
                              void* d_out, int out_size) {
    const float* x      = (const float*)d_in[0];
    const float* n1w    = (const float*)d_in[1];
    const float* n2w    = (const float*)d_in[2];
    const float* wq     = (const float*)d_in[3];
    const float* wk     = (const float*)d_in[4];
    const float* wv     = (const float*)d_in[5];
    const float* wo     = (const float*)d_in[6];
    const float* idx_wq = (const float*)d_in[7];
    const float* idx_wk = (const float*)d_in[8];
    const float* idx_ww = (const float*)d_in[9];
    const float* gate_w = (const float*)d_in[10];
    const float* w1     = (const float*)d_in[11];
    const float* b1     = (const float*)d_in[12];
    const float* w2     = (const float*)d_in[13];
    const float* b2     = (const float*)d_in[14];
    float* out = (float*)d_out;

    float *xn, *q, *qI, *kI, *wI, *sc, *x2, *xn2, *wd, *pr, *ffe;
    int *selidx, *selcnt, *ecnt, *elist;
    bf16 *kvb, *xnx, *xn2x, *aox, *hx, *wqkvx, *wox, *iwqx, *w1x, *w2x;
    cudaGetSymbolAddress((void**)&xn,  g_xn);
    cudaGetSymbolAddress((void**)&q,   g_q);
    cudaGetSymbolAddress((void**)&qI,  g_qI);
    cudaGetSymbolAddress((void**)&kI,  g_kI);
    cudaGetSymbolAddress((void**)&wI,  g_wI);
    cudaGetSymbolAddress((void**)&sc,  g_sc);
    cudaGetSymbolAddress((void**)&selidx, g_selidx);
    cudaGetSymbolAddress((void**)&selcnt, g_selcnt);
    cudaGetSymbolAddress((void**)&x2,  g_x2);
    cudaGetSymbolAddress((void**)&xn2, g_xn2);
    cudaGetSymbolAddress((void**)&wd,  g_wd);
    cudaGetSymbolAddress((void**)&pr,  g_pr);
    cudaGetSymbolAddress((void**)&ffe, g_ffe);
    cudaGetSymbolAddress((void**)&ecnt,  g_ecnt);
    cudaGetSymbolAddress((void**)&elist, g_elist);
    cudaGetSymbolAddress((void**)&kvb,  g_kvb);
    cudaGetSymbolAddress((void**)&xnx,  g_xnx);
    cudaGetSymbolAddress((void**)&xn2x, g_xn2x);
    cudaGetSymbolAddress((void**)&aox,  g_aox);
    cudaGetSymbolAddress((void**)&hx,   g_hx);
    cudaGetSymbolAddress((void**)&wqkvx, g_wqkvx);
    cudaGetSymbolAddress((void**)&wox,  g_wox);
    cudaGetSymbolAddress((void**)&iwqx, g_iwqx);
    cudaGetSymbolAddress((void**)&w1x,  g_w1x);
    cudaGetSymbolAddress((void**)&w2x,  g_w2x);

    const size_t WZ = (size_t)2 * Dz * Dz;

    // ---- weight split ([hi;lo]) ----
    convw_kernel<<<512, 256>>>(wq, wqkvx, Dz, 10);
    convw_kernel<<<512, 256>>>(wk, wqkvx + WZ, Dz, 10);
    convw_kernel<<<512, 256>>>(wv, wqkvx + 2 * WZ, Dz, 10);
    convw_kernel<<<512, 256>>>(wo, wox, Dz, 10);
    convw_kernel<<<128, 256>>>(idx_wq, iwqx, Dz, 8);
    for (int e = 0; e < Ez; e++) {
        convw_kernel<<<2048, 256>>>(w1 + (size_t)e * Dz * DFz,
                                    w1x + (size_t)e * 2 * Dz * DFz, Dz, 12);
        convw_kernel<<<2048, 256>>>(w2 + (size_t)e * DFz * Dz,
                                    w2x + (size_t)e * 2 * DFz * Dz, DFz, 10);
    }

    // ---- attention path ----
    rmsnorm2_kernel<<<Tz, 256>>>(x, n1w, xn, xnx);
    hgemm_kernel<5><<<dim3(8, 32, 3), 128>>>(xnx, wqkvx, q, kvb, Tz, Dz, Dz,
                                             nullptr, nullptr, nullptr, nullptr, nullptr,
                                             0, WZ, (size_t)Tz * Dz, 0);
    hgemm_kernel<0><<<dim3(2, 32), 128>>>(xnx, iwqx, qI, nullptr, Tz, HIz * DIz, Dz,
                                          nullptr, nullptr, nullptr, nullptr, nullptr,
                                          0, 0, 0, 0);
    sgemm_small_kernel<<<dim3(1, 32), 256>>>(xn, idx_wk, kI, Tz, DIz, Dz);
    sgemm_small_kernel<<<dim3(1, 32), 256>>>(xn, idx_ww, wI, Tz, HIz, Dz);

    idxscore_kernel<<<dim3(Sz / 64, Sz / 16, Bz), dim3(16, 16)>>>(qI, kI, wI, sc);
    topk_kernel<<<Tz, 256>>>(sc, selidx, selcnt);
    attn_kernel<<<Tz, 512>>>(q, kvb, kvb + (size_t)Tz * Dz, selidx, selcnt, aox);
    hgemm_kernel<1><<<dim3(8, 32), 128>>>(aox, wox, x2, nullptr, Tz, Dz, Dz,
                                          nullptr, x, nullptr, nullptr, nullptr,
                                          0, 0, 0, 0);

    // ---- MoE path (routed + expert-batched) ----
    rmsnorm2_kernel<<<Tz, 256>>>(x2, n2w, xn2, xn2x);
    gate_kernel<<<Tz, 256>>>(xn2, gate_w, wd, pr);
    route_zero_kernel<<<1, 32>>>(ecnt);
    route_kernel<<<Tz / 256, 256>>>(wd, ecnt, elist);
    route_pad_kernel<<<Ez, 128>>>(ecnt, elist);
    hgemm_kernel<2><<<dim3(32, 32, Ez), 128>>>(xn2x, w1x, nullptr, hx, Tz, DFz, Dz,
                                               b1, nullptr, nullptr, elist, ecnt,
                                               0, (size_t)2 * Dz * DFz,
                                               (size_t)Tz * 2 * DFz, DFz);
    hgemm_kernel<3><<<dim3(8, 32, Ez), 128>>>(hx, w2x, ffe, nullptr, Tz, Dz, DFz,
                                              b2, nullptr, wd, elist, ecnt,
                                              (size_t)Tz * 2 * DFz, (size_t)2 * DFz * Dz,
                                              (size_t)Tz * Dz, Dz);

    final_kernel<<<8192, 256>>>(x2, ffe, wd, out);
    aux_kernel<<<1, 256>>>(pr, wd, out + (out_size - 1));
}

// round 16
// speedup vs baseline: 1.6138x; 1.0072x over previous
#include <cuda_runtime.h>
#include <cuda_bf16.h>
#include <math.h>
#include <stdint.h>

// Problem dims (fixed by setup_inputs)
#define Bz 2
#define Sz 2048
#define Dz 1024
#define Tz 4096           // B*S
#define Hz 16
#define DHz 64
#define HIz 4
#define DIz 64
#define TKz 512
#define Ez 4
#define DFz 4096

typedef __nv_bfloat16 bf16;

// ---------------- scratch (device globals; no allocation allowed) --------------
__device__ float g_xn [Tz*Dz];
__device__ float g_q  [Tz*Dz];
__device__ float g_qI [Tz*HIz*DIz];
__device__ float g_kI [Tz*DIz];
__device__ float g_wI [Tz*HIz];
__device__ float g_sc [(size_t)Bz*Sz*Sz];
__device__ int   g_selidx[(size_t)Tz*TKz];
__device__ int   g_selcnt[Tz];
__device__ float g_x2 [Tz*Dz];
__device__ float g_xn2[Tz*Dz];
__device__ float g_wd [Tz*Ez];
__device__ float g_pr [Tz*Ez];
__device__ int   g_ecnt[Ez];
__device__ int   g_elist[Ez*Tz];
__device__ float g_ffe[(size_t)Ez*Tz*Dz];

// bf16 operands: split storage is [hi|lo] (2K); GEMM remaps k-blocks to get
// the 3-term product Ahi*Bhi + Ahi*Blo + Alo*Bhi.
__device__ bf16 g_kvb  [(size_t)2*Tz*Dz];
__device__ bf16 g_xnx  [(size_t)Tz*2*Dz];
__device__ bf16 g_xn2x [(size_t)Tz*2*Dz];
__device__ bf16 g_aox  [(size_t)Tz*2*Dz];
__device__ bf16 g_hx   [(size_t)Ez*Tz*2*DFz];
__device__ bf16 g_wqkvx[(size_t)3*2*Dz*Dz];
__device__ bf16 g_wox  [2*Dz*Dz];
__device__ bf16 g_iwqx [2*Dz*HIz*DIz];
__device__ bf16 g_w1x  [(size_t)Ez*2*Dz*DFz];
__device__ bf16 g_w2x  [(size_t)Ez*2*DFz*Dz];

// ---------------- helpers ------------------------------------------------------
__device__ __forceinline__ float gelu_f(float x) {
    float x3 = x * x * x;
    return 0.5f * x * (1.0f + tanhf(0.7978845608028654f * (x + 0.044715f * x3)));
}
__device__ __forceinline__ uint32_t smem_u32(const void* p) {
    return (uint32_t)__cvta_generic_to_shared(p);
}
__device__ __forceinline__ void ldsm4(uint32_t& r0, uint32_t& r1, uint32_t& r2,
                                      uint32_t& r3, uint32_t a) {
    asm volatile("ldmatrix.sync.aligned.m8n8.x4.shared.b16 {%0,%1,%2,%3}, [%4];\n"
                 : "=r"(r0), "=r"(r1), "=r"(r2), "=r"(r3) : "r"(a));
}
__device__ __forceinline__ void ldsm4t(uint32_t& r0, uint32_t& r1, uint32_t& r2,
                                       uint32_t& r3, uint32_t a) {
    asm volatile("ldmatrix.sync.aligned.m8n8.x4.trans.shared.b16 {%0,%1,%2,%3}, [%4];\n"
                 : "=r"(r0), "=r"(r1), "=r"(r2), "=r"(r3) : "r"(a));
}
__device__ __forceinline__ void mma_bf16(float c[4], uint32_t a0, uint32_t a1,
                                         uint32_t a2, uint32_t a3,
                                         uint32_t b0, uint32_t b1) {
    asm volatile("mma.sync.aligned.m16n8k16.row.col.f32.bf16.bf16.f32 "
                 "{%0,%1,%2,%3}, {%4,%5,%6,%7}, {%8,%9}, {%0,%1,%2,%3};\n"
                 : "+f"(c[0]), "+f"(c[1]), "+f"(c[2]), "+f"(c[3])
                 : "r"(a0), "r"(a1), "r"(a2), "r"(a3), "r"(b0), "r"(b1));
}
#define CPA16(dst, src) \
    asm volatile("cp.async.cg.shared.global [%0], [%1], 16;\n" :: "r"(dst), "l"(src))
#define CPA_COMMIT() asm volatile("cp.async.commit_group;\n" ::)
#define CPA_WAIT0()  asm volatile("cp.async.wait_group 0;\n" ::)

// ---------------- rmsnorm (fp32 out optional + bf16 [hi|lo] out) ---------------
__global__ void rmsnorm2_kernel(const float* __restrict__ x, const float* __restrict__ w,
                                float* __restrict__ y, bf16* __restrict__ yx) {
    int t = blockIdx.x;
    int tid = threadIdx.x;
    const float* xr = x + (size_t)t * Dz;
    float s = 0.f;
    for (int i = tid; i < Dz; i += 256) { float v = xr[i]; s += v * v; }
    __shared__ float red[256];
    red[tid] = s; __syncthreads();
    for (int off = 128; off; off >>= 1) {
        if (tid < off) red[tid] += red[tid + off];
        __syncthreads();
    }
    float inv = rsqrtf(red[0] * (1.0f / Dz) + 1e-6f);
    bf16* yr = yx + (size_t)t * 2 * Dz;
    for (int i = tid; i < Dz; i += 256) {
        float v = xr[i] * inv * w[i];
        if (y) y[(size_t)t * Dz + i] = v;
        bf16 hi = __float2bfloat16(v);
        bf16 lo = __float2bfloat16(v - __bfloat162float(hi));
        yr[i] = hi;
        yr[Dz + i] = lo;
    }
}

// ---------------- weight split: [K][N] fp32 -> [2K][N] bf16 [hi;lo] ------------
__global__ void convw_kernel(const float* __restrict__ src, bf16* __restrict__ dst,
                             int K, int logN) {
    unsigned nmask = (unsigned)((1 << logN) - 1);
    size_t total8 = ((size_t)K << logN) >> 3;
    for (size_t g = blockIdx.x * blockDim.x + threadIdx.x; g < total8;
         g += (size_t)gridDim.x * blockDim.x) {
        float4 a0 = ((const float4*)src)[g * 2];
        float4 a1 = ((const float4*)src)[g * 2 + 1];
        __align__(16) bf16 hv[8], lv[8];
        const float* f0 = (const float*)&a0;
        const float* f1 = (const float*)&a1;
#pragma unroll
        for (int q = 0; q < 4; q++) {
            bf16 hi = __float2bfloat16(f0[q]);
            hv[q] = hi;
            lv[q] = __float2bfloat16(f0[q] - __bfloat162float(hi));
        }
#pragma unroll
        for (int q = 0; q < 4; q++) {
            bf16 hi = __float2bfloat16(f1[q]);
            hv[4 + q] = hi;
            lv[4 + q] = __float2bfloat16(f1[q] - __bfloat162float(hi));
        }
        size_t base = g << 3;
        int k = (int)(base >> logN);
        int n = (int)(base & nmask);
        *(float4*)&dst[((size_t)k << logN) + n] = *(float4*)hv;
        *(float4*)&dst[((size_t)(K + k) << logN) + n] = *(float4*)lv;
    }
}

// ---------------- bf16 tensor-core GEMM (z-batched, 3-term remap) ---------------
template<int EPI>
__global__ void __launch_bounds__(128, 2)
hgemm_kernel(const bf16* __restrict__ A, const bf16* __restrict__ B,
             float* __restrict__ Cf, bf16* __restrict__ Cb,
             int M, int N, int Kthird,
             const float* __restrict__ bias, const float* __restrict__ resid,
             const float* __restrict__ wdv,
             const int* __restrict__ elist, const int* __restrict__ ecnt,
             size_t a_zs, size_t b_zs, size_t c_zs, int bias_zs) {
    int z = blockIdx.z;
    int bm = blockIdx.y * 128, bn = blockIdx.x * 128;
    int cnt = M;
    if (ecnt) {
        cnt = ecnt[z];
        int padded = (cnt + 127) & ~127;
        if (bm >= padded) return;
    }
    A += (size_t)z * a_zs;
    B += (size_t)z * b_zs;
    if (bias) bias += (size_t)z * bias_zs;
    const int* lst = elist ? elist + (size_t)z * Tz : nullptr;

    __shared__ __align__(16) bf16 As[2][128][40];
    __shared__ __align__(16) bf16 Bs[2][32][136];
    int tid = threadIdx.x;
    int warp = tid >> 5, lane = tid & 31;
    int wm = (warp & 1) * 64, wn = (warp >> 1) * 64;

    const int KB = Kthird >> 5;
    const int KT = 3 * KB;
    const int AS = 2 * Kthird;

    int arow = tid >> 2, acol = (tid & 3) * 8;
    int brow = tid >> 4, bcol = (tid & 15) * 8;
    const bf16* Ag[4];
#pragma unroll
    for (int j = 0; j < 4; j++) {
        int r = bm + arow + 32 * j;
        if (EPI == 2) r = lst[r];
        Ag[j] = A + (size_t)r * AS + acol;
    }
    const bf16* Bg = B + (size_t)brow * N + bn + bcol;

    float c[4][8][4];
#pragma unroll
    for (int mi = 0; mi < 4; mi++)
#pragma unroll
        for (int ni = 0; ni < 8; ni++)
#pragma unroll
            for (int j = 0; j < 4; j++) c[mi][ni][j] = 0.f;

    {
#pragma unroll
        for (int j = 0; j < 4; j++)
            CPA16(smem_u32(&As[0][arow + 32 * j][acol]), Ag[j]);
#pragma unroll
        for (int j = 0; j < 4; j++)
            CPA16(smem_u32(&Bs[0][brow + 8 * j][bcol]), Bg + (size_t)(8 * j) * N);
        CPA_COMMIT();
    }
    int buf = 0;
    for (int kt = 0; kt < KT; kt++) {
        CPA_WAIT0();
        __syncthreads();
        if (kt + 1 < KT) {
            int nb = buf ^ 1;
            int k2 = kt + 1;
            int ak = (k2 < KB) ? k2 : k2 - KB;
            int bk = (k2 < 2 * KB) ? k2 : k2 - 2 * KB;
#pragma unroll
            for (int j = 0; j < 4; j++)
                CPA16(smem_u32(&As[nb][arow + 32 * j][acol]), Ag[j] + ak * 32);
#pragma unroll
            for (int j = 0; j < 4; j++)
                CPA16(smem_u32(&Bs[nb][brow + 8 * j][bcol]),
                      Bg + (size_t)(bk * 32 + 8 * j) * N);
            CPA_COMMIT();
        }
#pragma unroll
        for (int kk = 0; kk < 32; kk += 16) {
            uint32_t a[4][4], b[8][2];
#pragma unroll
            for (int mi = 0; mi < 4; mi++) {
                uint32_t addr = smem_u32(
                    &As[buf][wm + mi * 16 + (lane & 15)][kk + ((lane >> 4) << 3)]);
                ldsm4(a[mi][0], a[mi][1], a[mi][2], a[mi][3], addr);
            }
#pragma unroll
            for (int nj = 0; nj < 4; nj++) {
                uint32_t addr = smem_u32(
                    &Bs[buf][kk + (lane & 15)][wn + nj * 16 + ((lane >> 4) << 3)]);
                ldsm4t(b[2 * nj][0], b[2 * nj][1], b[2 * nj + 1][0], b[2 * nj + 1][1], addr);
            }
#pragma unroll
            for (int mi = 0; mi < 4; mi++)
#pragma unroll
                for (int ni = 0; ni < 8; ni++)
                    mma_bf16(c[mi][ni], a[mi][0], a[mi][1], a[mi][2], a[mi][3],
                             b[ni][0], b[ni][1]);
        }
        buf ^= 1;
    }

#pragma unroll
    for (int mi = 0; mi < 4; mi++) {
#pragma unroll
        for (int rr = 0; rr < 2; rr++) {
            int r = bm + wm + mi * 16 + (lane >> 2) + rr * 8;
            if (EPI == 3) {
                if (r < cnt) {
                    int tok = lst[r];
                    float rsc = wdv[(size_t)tok * Ez + z];
                    float* dst = Cf + (size_t)z * c_zs;
#pragma unroll
                    for (int ni = 0; ni < 8; ni++)
#pragma unroll
                        for (int cc = 0; cc < 2; cc++) {
                            int col = bn + wn + ni * 8 + (lane & 3) * 2 + cc;
                            dst[(size_t)tok * N + col] =
                                rsc * (c[mi][ni][rr * 2 + cc] + bias[col]);
                        }
                }
            } else if (EPI == 5) {
                if (z == 0) {
#pragma unroll
                    for (int ni = 0; ni < 8; ni++)
#pragma unroll
                        for (int cc = 0; cc < 2; cc++) {
                            int col = bn + wn + ni * 8 + (lane & 3) * 2 + cc;
                            Cf[(size_t)r * N + col] = c[mi][ni][rr * 2 + cc];
                        }
                } else {
                    bf16* dst = Cb + (size_t)(z - 1) * c_zs;
#pragma unroll
                    for (int ni = 0; ni < 8; ni++) {
                        int colb = bn + wn + ni * 8 + (lane & 3) * 2;
                        __nv_bfloat162 p;
                        p.x = __float2bfloat16(c[mi][ni][rr * 2]);
                        p.y = __float2bfloat16(c[mi][ni][rr * 2 + 1]);
                        *(__nv_bfloat162*)&dst[(size_t)r * N + colb] = p;
                    }
                }
            } else if (EPI == 2) {
                bf16* dstb = Cb + (size_t)z * c_zs;
#pragma unroll
                for (int ni = 0; ni < 8; ni++)
#pragma unroll
                    for (int cc = 0; cc < 2; cc++) {
                        int col = bn + wn + ni * 8 + (lane & 3) * 2 + cc;
                        float g = gelu_f(c[mi][ni][rr * 2 + cc] + bias[col]);
                        bf16 hi = __float2bfloat16(g);
                        bf16 lo = __float2bfloat16(g - __bfloat162float(hi));
                        size_t base = (size_t)r * 2 * N;
                        dstb[base + col] = hi;
                        dstb[base + N + col] = lo;
                    }
            } else {
#pragma unroll
                for (int ni = 0; ni < 8; ni++)
#pragma unroll
                    for (int cc = 0; cc < 2; cc++) {
                        int col = bn + wn + ni * 8 + (lane & 3) * 2 + cc;
                        float val = c[mi][ni][rr * 2 + cc];
                        if (EPI == 0) Cf[(size_t)r * N + col] = val;
                        else          Cf[(size_t)r * N + col] = val + resid[(size_t)r * N + col];
                    }
            }
        }
    }
}

// ---------------- small fp32 GEMM (kI: N=64, wI: N=4) --------------------------
__global__ void __launch_bounds__(256, 2)
sgemm_small_kernel(const float* __restrict__ A, const float* __restrict__ B,
                   float* __restrict__ C, int M, int N, int K) {
    const int BM = 128, BN = 128, BK = 8, TM = 8, TN = 8;
    __shared__ float As[BK][BM];
    __shared__ float Bs[BK][BN];
    int tid = threadIdx.x;
    int bm = blockIdx.y * BM;
    int bn = blockIdx.x * BN;
    int trow = (tid / 16) * TM;
    int tcol = (tid % 16) * TN;
    float acc[TM][TN];
#pragma unroll
    for (int i = 0; i < TM; i++)
#pragma unroll
        for (int j = 0; j < TN; j++) acc[i][j] = 0.f;
    int arow = tid >> 1, acol = (tid & 1) * 4;
    int brow = tid >> 5, bcol = (tid & 31) * 4;
    const float* Aptr = A + (size_t)(bm + arow) * K;
    for (int k0 = 0; k0 < K; k0 += BK) {
        float4 av = *(const float4*)(Aptr + k0 + acol);
        As[acol + 0][arow] = av.x; As[acol + 1][arow] = av.y;
        As[acol + 2][arow] = av.z; As[acol + 3][arow] = av.w;
        int bc = bn + bcol;
#pragma unroll
        for (int j = 0; j < 4; j++)
            Bs[brow][bcol + j] = (bc + j < N) ? B[(size_t)(k0 + brow) * N + bc + j] : 0.f;
        __syncthreads();
#pragma unroll
        for (int kk = 0; kk < BK; kk++) {
            float ar[TM], br[TN];
#pragma unroll
            for (int i = 0; i < TM; i++) ar[i] = As[kk][trow + i];
#pragma unroll
            for (int j = 0; j < TN; j++) br[j] = Bs[kk][tcol + j];
#pragma unroll
            for (int i = 0; i < TM; i++)
#pragma unroll
                for (int j = 0; j < TN; j++) acc[i][j] += ar[i] * br[j];
        }
        __syncthreads();
    }
#pragma unroll
    for (int i = 0; i < TM; i++) {
        int r = bm + trow + i;
#pragma unroll
        for (int j = 0; j < TN; j++) {
            int cidx = bn + tcol + j;
            if (cidx < N) C[(size_t)r * N + cidx] = acc[i][j];
        }
    }
}

// ---------------- indexer scores ------------------------------------------------
__global__ void idxscore_kernel(const float* __restrict__ qI, const float* __restrict__ kI,
                                const float* __restrict__ wI, float* __restrict__ sc) {
    int b  = blockIdx.z;
    int t0 = blockIdx.y * 16;
    int s0 = blockIdx.x * 64;
    if (s0 > t0 + 15) return;
    __shared__ float qIs[16][257];
    __shared__ float kIs[64][65];
    __shared__ float wIs[16][4];
    int tx = threadIdx.x, ty = threadIdx.y;
    int tid = ty * 16 + tx;
    for (int idx = tid; idx < 16 * 256; idx += 256) {
        int r = idx >> 8, c = idx & 255;
        qIs[r][c] = qI[((size_t)(b * Sz + t0 + r)) * 256 + c];
    }
    for (int idx = tid; idx < 64 * 64; idx += 256) {
        int r = idx >> 6, c = idx & 63;
        kIs[r][c] = kI[((size_t)(b * Sz + s0 + r)) * 64 + c];
    }
    if (tid < 64) wIs[tid >> 2][tid & 3] = wI[((size_t)(b * Sz + (tid >> 2) + t0)) * 4 + (tid & 3)];
    __syncthreads();

    float acc4[4] = {0.f, 0.f, 0.f, 0.f};
#pragma unroll
    for (int h = 0; h < 4; h++) {
        float dot[4] = {0.f, 0.f, 0.f, 0.f};
#pragma unroll
        for (int d = 0; d < 64; d++) {
            float qv = qIs[ty][h * 64 + d];
            dot[0] += qv * kIs[tx +  0][d];
            dot[1] += qv * kIs[tx + 16][d];
            dot[2] += qv * kIs[tx + 32][d];
            dot[3] += qv * kIs[tx + 48][d];
        }
        float wv = wIs[ty][h];
#pragma unroll
        for (int j = 0; j < 4; j++) acc4[j] += wv * fmaxf(dot[j], 0.f);
    }
    int t = t0 + ty;
#pragma unroll
    for (int j = 0; j < 4; j++) {
        int s = s0 + tx + 16 * j;
        if (s <= t) sc[((size_t)(b * Sz + t)) * Sz + s] = acc4[j];
    }
}

// ---------------- top-k (512) per (b,t): radix select, jax tie-break -----------
__global__ void topk_kernel(const float* __restrict__ sc, int* __restrict__ selidx,
                            int* __restrict__ selcnt) {
    int bt = blockIdx.x;
    int t = bt & (Sz - 1);
    int n = t + 1;
    int tid = threadIdx.x;
    int* outp = selidx + (size_t)bt * TKz;
    if (n <= TKz) {
        for (int i = tid; i < n; i += 256) outp[i] = i;
        if (tid == 0) selcnt[bt] = n;
        return;
    }
    const float* row = sc + (size_t)bt * Sz;
    __shared__ unsigned keys[Sz];
    for (int i = tid; i < n; i += 256) {
        unsigned u = __float_as_uint(row[i]);
        keys[i] = (u & 0x80000000u) ? ~u : (u | 0x80000000u);
    }
    __shared__ int hist[256];
    __shared__ unsigned p_s;
    __shared__ int need_s;
    if (tid == 0) { p_s = 0; need_s = TKz; }
    __syncthreads();
    for (int byte = 3; byte >= 0; byte--) {
        int sh = byte * 8;
        for (int i = tid; i < 256; i += 256) hist[i] = 0;
        __syncthreads();
        unsigned p = p_s;
        unsigned mask_hi = (byte == 3) ? 0u : (0xFFFFFFFFu << (sh + 8));
        for (int i = tid; i < n; i += 256) {
            unsigned k = keys[i];
            if ((k & mask_hi) == p) atomicAdd(&hist[(k >> sh) & 255u], 1);
        }
        __syncthreads();
        if (tid == 0) {
            int need = need_s;
            int acc = 0;
            int chosen = 0;
            for (int b2 = 255; b2 >= 0; b2--) {
                if (acc + hist[b2] >= need) { chosen = b2; break; }
                acc += hist[b2];
            }
            need_s = need - acc;
            p_s = p | ((unsigned)chosen << sh);
        }
        __syncthreads();
    }
    unsigned p = p_s;   // exact TKz-th largest key
    __shared__ int pos;
    if (tid == 0) pos = 0;
    __syncthreads();
    for (int i = tid; i < n; i += 256)
        if (keys[i] > p) { int j = atomicAdd(&pos, 1); outp[j] = i; }
    __syncthreads();
    if (tid == 0) {
        int j = pos;
        for (int i = 0; i < n && j < TKz; i++)
            if (keys[i] == p) outp[j++] = i;
        selcnt[bt] = TKz;
    }
}

// ---------------- sparse attention (bf16 K/V), two-phase ------------------------
__global__ void __launch_bounds__(512)
attn_kernel(const float* __restrict__ q, const bf16* __restrict__ kb,
            const bf16* __restrict__ vb, const int* __restrict__ selidx,
            const int* __restrict__ selcnt, bf16* __restrict__ aox) {
    int bt = blockIdx.x;
    int b = bt >> 11;
    int tid = threadIdx.x;
    __shared__ float qs[Hz * DHz];
    __shared__ int sels[TKz + 4];
    __shared__ float sscore[Hz][TKz];
    int n = selcnt[bt];
    int n4 = (n + 3) & ~3;
    for (int i = tid; i < Dz; i += 512) qs[i] = q[(size_t)bt * Dz + i];
    for (int i = tid; i < n; i += 512) sels[i] = selidx[(size_t)bt * TKz + i];
    if (tid < 4) sels[n + tid] = selidx[(size_t)bt * TKz];   // pad with sel 0
    __syncthreads();
    int h = tid >> 5, lane = tid & 31;
    float q0 = qs[h * 64 + 2 * lane], q1 = qs[h * 64 + 2 * lane + 1];
    size_t hoff = h * 64 + 2 * lane;
    float m = -3.0e38f;
    for (int i = 0; i < n4; i += 4) {
        float part[4];
#pragma unroll
        for (int j = 0; j < 4; j++) {
            int s = sels[i + j];
            float2 kf = __bfloat1622float2(
                *(const __nv_bfloat162*)(kb + ((size_t)(b * Sz + s)) * Dz + hoff));
            part[j] = q0 * kf.x + q1 * kf.y;
        }
#pragma unroll
        for (int off = 16; off; off >>= 1)
#pragma unroll
            for (int j = 0; j < 4; j++)
                part[j] += __shfl_xor_sync(0xffffffffu, part[j], off);
#pragma unroll
        for (int j = 0; j < 4; j++) {
            float scv = part[j] * 0.125f;
            sscore[h][i + j] = scv;
            m = fmaxf(m, scv);
        }
    }
    float l = 0.f, o0 = 0.f, o1 = 0.f;
#pragma unroll 4
    for (int i = 0; i < n; i++) {
        float pw = __expf(sscore[h][i] - m);
        int s = sels[i];
        float2 vf = __bfloat1622float2(
            *(const __nv_bfloat162*)(vb + ((size_t)(b * Sz + s)) * Dz + hoff));
        o0 += pw * vf.x;
        o1 += pw * vf.y;
        l += pw;
    }
    float inv = 1.0f / l;
    o0 *= inv; o1 *= inv;
    size_t base = (size_t)bt * 2 * Dz;
    int c0 = h * 64 + 2 * lane, c1 = c0 + 1;
    bf16 h0 = __float2bfloat16(o0);
    bf16 l0 = __float2bfloat16(o0 - __bfloat162float(h0));
    bf16 h1 = __float2bfloat16(o1);
    bf16 l1 = __float2bfloat16(o1 - __bfloat162float(h1));
    aox[base + c0] = h0;       aox[base + c1] = h1;
    aox[base + Dz + c0] = l0;  aox[base + Dz + c1] = l1;
}

// ---------------- gate: softmax(4) + top-2 + combine weights -------------------
__global__ void gate_kernel(const float* __restrict__ xn2, const float* __restrict__ gw,
                            float* __restrict__ wdense, float* __restrict__ probsb) {
    int t = blockIdx.x;
    int tid = threadIdx.x;
    const float* xr = xn2 + (size_t)t * Dz;
    float le[4] = {0.f, 0.f, 0.f, 0.f};
    for (int d = tid; d < Dz; d += 256) {
        float xv = xr[d];
        const float* g = gw + (size_t)d * 4;
        le[0] += xv * g[0]; le[1] += xv * g[1];
        le[2] += xv * g[2]; le[3] += xv * g[3];
    }
    __shared__ float red[4][256];
    for (int e = 0; e < 4; e++) red[e][tid] = le[e];
    __syncthreads();
    for (int off = 128; off; off >>= 1) {
        if (tid < off)
            for (int e = 0; e < 4; e++) red[e][tid] += red[e][tid + off];
        __syncthreads();
    }
    if (tid == 0) {
        float lg[4], pr[4];
        float mx = -3.0e38f;
        for (int e = 0; e < 4; e++) { lg[e] = red[e][0]; mx = fmaxf(mx, lg[e]); }
        float sum = 0.f;
        for (int e = 0; e < 4; e++) { pr[e] = expf(lg[e] - mx); sum += pr[e]; }
        float inv = 1.0f / sum;
        for (int e = 0; e < 4; e++) { pr[e] *= inv; probsb[(size_t)t * 4 + e] = pr[e]; }
        int i1 = 0;
        for (int e = 1; e < 4; e++) if (pr[e] > pr[i1]) i1 = e;
        int i2 = -1; float b2v = -1.f;
        for (int e = 0; e < 4; e++) if (e != i1 && pr[e] > b2v) { b2v = pr[e]; i2 = e; }
        float wsum = pr[i1] + pr[i2];
        float wd[4] = {0.f, 0.f, 0.f, 0.f};
        wd[i1] = pr[i1] / wsum;
        wd[i2] = pr[i2] / wsum;
        for (int e = 0; e < 4; e++) wdense[(size_t)t * 4 + e] = wd[e];
    }
}

// ---------------- routing -------------------------------------------------------
__global__ void route_zero_kernel(int* __restrict__ ecnt) {
    if (threadIdx.x < Ez) ecnt[threadIdx.x] = 0;
}
__global__ void route_kernel(const float* __restrict__ wd, int* __restrict__ ecnt,
                             int* __restrict__ elist) {
    int t = blockIdx.x * blockDim.x + threadIdx.x;
    if (t < Tz) {
#pragma unroll
        for (int e = 0; e < Ez; e++)
            if (wd[(size_t)t * Ez + e] > 0.f) {
                int p = atomicAdd(&ecnt[e], 1);
                elist[e * Tz + p] = t;
            }
    }
}
__global__ void route_pad_kernel(const int* __restrict__ ecnt, int* __restrict__ elist) {
    int e = blockIdx.x;
    int cnt = ecnt[e];
    int padded = (cnt + 127) & ~127;
    for (int i = cnt + threadIdx.x; i < padded; i += blockDim.x) elist[e * Tz + i] = 0;
}

// ---------------- aux loss ------------------------------------------------------
__global__ void aux_kernel(const float* __restrict__ probsb, const float* __restrict__ wdense,
                           float* __restrict__ out_aux) {
    int tid = threadIdx.x;
    float sP[4] = {0.f, 0.f, 0.f, 0.f}, sF[4] = {0.f, 0.f, 0.f, 0.f};
    for (int t = tid; t < Tz; t += 256)
        for (int e = 0; e < 4; e++) {
            sP[e] += probsb[(size_t)t * 4 + e];
            sF[e] += (wdense[(size_t)t * 4 + e] > 0.f) ? 1.f : 0.f;
        }
    __shared__ float rP[4][256], rF[4][256];
    for (int e = 0; e < 4; e++) { rP[e][tid] = sP[e]; rF[e][tid] = sF[e]; }
    __syncthreads();
    for (int off = 128; off; off >>= 1) {
        if (tid < off)
            for (int e = 0; e < 4; e++) {
                rP[e][tid] += rP[e][tid + off];
                rF[e][tid] += rF[e][tid + off];
            }
        __syncthreads();
    }
    if (tid == 0) {
        float aux = 0.f;
        for (int e = 0; e < 4; e++)
            aux += (rF[e][0] * (1.0f / Tz)) * (rP[e][0] * (1.0f / Tz));
        *out_aux = (float)Ez * aux;
    }
}

// ---------------- final: out = x2 + sum_e masked ffe[e] -------------------------
__global__ void final_kernel(const float* __restrict__ x2, const float* __restrict__ ffe,
                             const float* __restrict__ wd, float* __restrict__ out) {
    for (int i = blockIdx.x * blockDim.x + threadIdx.x; i < Tz * Dz;
         i += gridDim.x * blockDim.x) {
        int t = i >> 10;
        float s = x2[i];
#pragma unroll
        for (int e = 0; e < Ez; e++)
            if (wd[(size_t)t * Ez + e] > 0.f) s += ffe[(size_t)e * Tz * Dz + i];
        out[i] = s;
    }
}

// ---------------- launch (multi-stream fork/join for graph capture) -------------
extern "C" void kernel_launch(void* const* d_in, const int* in_sizes, int n_in,
                              void* d_out, int out_size) {
    const float* x      = (const float*)d_in[0];
    const float* n1w    = (const float*)d_in[1];
    const float* n2w    = (const float*)d_in[2];
    const float* wq     = (const float*)d_in[3];
    const float* wk     = (const float*)d_in[4];
    const float* wv     = (const float*)d_in[5];
    const float* wo     = (const float*)d_in[6];
    const float* idx_wq = (const float*)d_in[7];
    const float* idx_wk = (const float*)d_in[8];
    const float* idx_ww = (const float*)d_in[9];
    const float* gate_w = (const float*)d_in[10];
    const float* w1     = (const float*)d_in[11];
    const float* b1     = (const float*)d_in[12];
    const float* w2     = (const float*)d_in[13];
    const float* b2     = (const float*)d_in[14];
    float* out = (float*)d_out;

    float *xn, *q, *qI, *kI, *wI, *sc, *x2, *xn2, *wd, *pr, *ffe;
    int *selidx, *selcnt, *ecnt, *elist;
    bf16 *kvb, *xnx, *xn2x, *aox, *hx, *wqkvx, *wox, *iwqx, *w1x, *w2x;
    cudaGetSymbolAddress((void**)&xn,  g_xn);
    cudaGetSymbolAddress((void**)&q,   g_q);
    cudaGetSymbolAddress((void**)&qI,  g_qI);
    cudaGetSymbolAddress((void**)&kI,  g_kI);
    cudaGetSymbolAddress((void**)&wI,  g_wI);
    cudaGetSymbolAddress((void**)&sc,  g_sc);
    cudaGetSymbolAddress((void**)&selidx, g_selidx);
    cudaGetSymbolAddress((void**)&selcnt, g_selcnt);
    cudaGetSymbolAddress((void**)&x2,  g_x2);
    cudaGetSymbolAddress((void**)&xn2, g_xn2);
    cudaGetSymbolAddress((void**)&wd,  g_wd);
    cudaGetSymbolAddress((void**)&pr,  g_pr);
    cudaGetSymbolAddress((void**)&ffe, g_ffe);
    cudaGetSymbolAddress((void**)&ecnt,  g_ecnt);
    cudaGetSymbolAddress((void**)&elist, g_elist);
    cudaGetSymbolAddress((void**)&kvb,  g_kvb);
    cudaGetSymbolAddress((void**)&xnx,  g_xnx);
    cudaGetSymbolAddress((void**)&xn2x, g_xn2x);
    cudaGetSymbolAddress((void**)&aox,  g_aox);
    cudaGetSymbolAddress((void**)&hx,   g_hx);
    cudaGetSymbolAddress((void**)&wqkvx, g_wqkvx);
    cudaGetSymbolAddress((void**)&wox,  g_wox);
    cudaGetSymbolAddress((void**)&iwqx, g_iwqx);
    cudaGetSymbolAddress((void**)&w1x,  g_w1x);
    cudaGetSymbolAddress((void**)&w2x,  g_w2x);

    static cudaStream_t s1 = nullptr, s2 = nullptr;
    static cudaEvent_t e0, e1, eTopk, eConv;
    if (!s1) {
        cudaStreamCreateWithFlags(&s1, cudaStreamNonBlocking);
        cudaStreamCreateWithFlags(&s2, cudaStreamNonBlocking);
        cudaEventCreateWithFlags(&e0, cudaEventDisableTiming);
        cudaEventCreateWithFlags(&e1, cudaEventDisableTiming);
        cudaEventCreateWithFlags(&eTopk, cudaEventDisableTiming);
        cudaEventCreateWithFlags(&eConv, cudaEventDisableTiming);
    }

    const size_t WZ = (size_t)2 * Dz * Dz;

    // fork
    cudaEventRecord(e0, 0);
    cudaStreamWaitEvent(s1, e0, 0);
    cudaStreamWaitEvent(s2, e0, 0);

    // s1: MoE weight conversions (join before w1 GEMM)
    for (int e = 0; e < Ez; e++) {
        convw_kernel<<<2048, 256, 0, s1>>>(w1 + (size_t)e * Dz * DFz,
                                           w1x + (size_t)e * 2 * Dz * DFz, Dz, 12);
        convw_kernel<<<2048, 256, 0, s1>>>(w2 + (size_t)e * DFz * Dz,
                                           w2x + (size_t)e * 2 * DFz * Dz, DFz, 10);
    }
    cudaEventRecord(eConv, s1);

    // s0: attention weights + norm1
    convw_kernel<<<512, 256>>>(wq, wqkvx, Dz, 10);
    convw_kernel<<<512, 256>>>(wk, wqkvx + WZ, Dz, 10);
    convw_kernel<<<512, 256>>>(wv, wqkvx + 2 * WZ, Dz, 10);
    convw_kernel<<<512, 256>>>(wo, wox, Dz, 10);
    rmsnorm2_kernel<<<Tz, 256>>>(x, n1w, xn, xnx);
    cudaEventRecord(e1, 0);

    // s2: indexer chain (iwqx conv has no deps; rest needs norm1)
    convw_kernel<<<128, 256, 0, s2>>>(idx_wq, iwqx, Dz, 8);
    cudaStreamWaitEvent(s2, e1, 0);
    sgemm_small_kernel<<<dim3(1, 32), 256, 0, s2>>>(xn, idx_wk, kI, Tz, DIz, Dz);
    sgemm_small_kernel<<<dim3(1, 32), 256, 0, s2>>>(xn, idx_ww, wI, Tz, HIz, Dz);
    hgemm_kernel<0><<<dim3(2, 32), 128, 0, s2>>>(xnx, iwqx, qI, nullptr,
                                                 Tz, HIz * DIz, Dz,
                                                 nullptr, nullptr, nullptr, nullptr,
                                                 nullptr, 0, 0, 0, 0);
    idxscore_kernel<<<dim3(Sz / 64, Sz / 16, Bz), dim3(16, 16), 0, s2>>>(qI, kI, wI, sc);
    topk_kernel<<<Tz, 256, 0, s2>>>(sc, selidx, selcnt);
    cudaEventRecord(eTopk, s2);

    // s0: QKV (overlaps the s2 chain), then join for attention
    hgemm_kernel<5><<<dim3(8, 32, 3), 128>>>(xnx, wqkvx, q, kvb, Tz, Dz, Dz,
                                             nullptr, nullptr, nullptr, nullptr, nullptr,
                                             0, WZ, (size_t)Tz * Dz, 0);
    cudaStreamWaitEvent(0, eTopk, 0);
    attn_kernel<<<Tz, 512>>>(q, kvb, kvb + (size_t)Tz * Dz, selidx, selcnt, aox);
    hgemm_kernel<1><<<dim3(8, 32), 128>>>(aox, wox, x2, nullptr, Tz, Dz, Dz,
                                          nullptr, x, nullptr, nullptr, nullptr,
                                          0, 0, 0, 0);

    // ---- MoE path (routed + expert-batched) ----
    rmsnorm2_kernel<<<Tz, 256>>>(x2, n2w, xn2, xn2x);
    gate_kernel<<<Tz, 256>>>(xn2, gate_w, wd, pr);
    route_zero_kernel<<<1, 32>>>(ecnt);
    route_kernel<<<Tz / 256, 256>>>(wd, ecnt, elist);
    route_pad_kernel<<<Ez, 128>>>(ecnt, elist);
    cudaStreamWaitEvent(0, eConv, 0);
    hgemm_kernel<2><<<dim3(32, 32, Ez), 128>>>(xn2x, w1x, nullptr, hx, Tz, DFz, Dz,
                                               b1, nullptr, nullptr, elist, ecnt,
                                               0, (size_t)2 * Dz * DFz,
                                               (size_t)Tz * 2 * DFz, DFz);
    hgemm_kernel<3><<<dim3(8, 32, Ez), 128>>>(hx, w2x, ffe, nullptr, Tz, Dz, DFz,
                                              b2, nullptr, wd, elist, ecnt,
                                              (size_t)Tz * 2 * DFz, (size_t)2 * DFz * Dz,
                                              (size_t)Tz * Dz, Dz);

    final_kernel<<<8192, 256>>>(x2, ffe, wd, out);
    aux_kernel<<<1, 256>>>(pr, wd, out + (out_size - 1));
}

// round 17
// speedup vs baseline: 1.6906x; 1.0476x over previous
#include <cuda_runtime.h>
#include <cuda_bf16.h>
#include <math.h>
#include <stdint.h>

// Problem dims (fixed by setup_inputs)
#define Bz 2
#define Sz 2048
#define Dz 1024
#define Tz 4096           // B*S
#define Hz 16
#define DHz 64
#define HIz 4
#define DIz 64
#define TKz 512
#define Ez 4
#define DFz 4096

typedef __nv_bfloat16 bf16;

// ---------------- scratch (device globals; no allocation allowed) --------------
__device__ float g_xn [Tz*Dz];
__device__ float g_q  [Tz*Dz];
__device__ float g_qI [Tz*HIz*DIz];
__device__ float g_kI [Tz*DIz];
__device__ float g_wI [Tz*HIz];
__device__ float g_sc [(size_t)Bz*Sz*Sz];
__device__ int   g_selidx[(size_t)Tz*TKz];
__device__ int   g_selcnt[Tz];
__device__ float g_x2 [Tz*Dz];
__device__ float g_xn2[Tz*Dz];
__device__ float g_wd [Tz*Ez];
__device__ float g_pr [Tz*Ez];
__device__ int   g_ecnt[Ez];
__device__ int   g_elist[Ez*Tz];
__device__ float g_ffe[(size_t)Ez*Tz*Dz];

// bf16 operands: split storage is [hi|lo] (2K); GEMM remaps k-blocks to get
// the 3-term product Ahi*Bhi + Ahi*Blo + Alo*Bhi.
__device__ bf16 g_kvb  [(size_t)2*Tz*Dz];
__device__ bf16 g_xnx  [(size_t)Tz*2*Dz];
__device__ bf16 g_xn2x [(size_t)Tz*2*Dz];
__device__ bf16 g_aox  [(size_t)Tz*2*Dz];
__device__ bf16 g_hx   [(size_t)Ez*Tz*2*DFz];
__device__ bf16 g_wqkvx[(size_t)3*2*Dz*Dz];
__device__ bf16 g_wox  [2*Dz*Dz];
__device__ bf16 g_iwqx [2*Dz*HIz*DIz];
__device__ bf16 g_w1x  [(size_t)Ez*2*Dz*DFz];
__device__ bf16 g_w2x  [(size_t)Ez*2*DFz*Dz];

// ---------------- helpers ------------------------------------------------------
__device__ __forceinline__ float gelu_f(float x) {
    float x3 = x * x * x;
    return 0.5f * x * (1.0f + tanhf(0.7978845608028654f * (x + 0.044715f * x3)));
}
__device__ __forceinline__ uint32_t smem_u32(const void* p) {
    return (uint32_t)__cvta_generic_to_shared(p);
}
__device__ __forceinline__ void ldsm4(uint32_t& r0, uint32_t& r1, uint32_t& r2,
                                      uint32_t& r3, uint32_t a) {
    asm volatile("ldmatrix.sync.aligned.m8n8.x4.shared.b16 {%0,%1,%2,%3}, [%4];\n"
                 : "=r"(r0), "=r"(r1), "=r"(r2), "=r"(r3) : "r"(a));
}
__device__ __forceinline__ void ldsm4t(uint32_t& r0, uint32_t& r1, uint32_t& r2,
                                       uint32_t& r3, uint32_t a) {
    asm volatile("ldmatrix.sync.aligned.m8n8.x4.trans.shared.b16 {%0,%1,%2,%3}, [%4];\n"
                 : "=r"(r0), "=r"(r1), "=r"(r2), "=r"(r3) : "r"(a));
}
__device__ __forceinline__ void mma_bf16(float c[4], uint32_t a0, uint32_t a1,
                                         uint32_t a2, uint32_t a3,
                                         uint32_t b0, uint32_t b1) {
    asm volatile("mma.sync.aligned.m16n8k16.row.col.f32.bf16.bf16.f32 "
                 "{%0,%1,%2,%3}, {%4,%5,%6,%7}, {%8,%9}, {%0,%1,%2,%3};\n"
                 : "+f"(c[0]), "+f"(c[1]), "+f"(c[2]), "+f"(c[3])
                 : "r"(a0), "r"(a1), "r"(a2), "r"(a3), "r"(b0), "r"(b1));
}
#define CPA16(dst, src) \
    asm volatile("cp.async.cg.shared.global [%0], [%1], 16;\n" :: "r"(dst), "l"(src))
#define CPA_COMMIT() asm volatile("cp.async.commit_group;\n" ::)
#define CPA_WAIT0()  asm volatile("cp.async.wait_group 0;\n" ::)
#define CPA_WAIT1()  asm volatile("cp.async.wait_group 1;\n" ::)

// smem ring for hgemm (3-stage, dynamic)
#define AS_BYTES (128 * 40 * 2)     // 10240
#define BS_BYTES (32 * 136 * 2)     // 8704
#define STAGE_BYTES (AS_BYTES + BS_BYTES)
#define HG_SMEM (3 * STAGE_BYTES)   // 56832

// ---------------- rmsnorm (fp32 out optional + bf16 [hi|lo] out) ---------------
__global__ void rmsnorm2_kernel(const float* __restrict__ x, const float* __restrict__ w,
                                float* __restrict__ y, bf16* __restrict__ yx) {
    int t = blockIdx.x;
    int tid = threadIdx.x;
    const float* xr = x + (size_t)t * Dz;
    float s = 0.f;
    for (int i = tid; i < Dz; i += 256) { float v = xr[i]; s += v * v; }
    __shared__ float red[256];
    red[tid] = s; __syncthreads();
    for (int off = 128; off; off >>= 1) {
        if (tid < off) red[tid] += red[tid + off];
        __syncthreads();
    }
    float inv = rsqrtf(red[0] * (1.0f / Dz) + 1e-6f);
    bf16* yr = yx + (size_t)t * 2 * Dz;
    for (int i = tid; i < Dz; i += 256) {
        float v = xr[i] * inv * w[i];
        if (y) y[(size_t)t * Dz + i] = v;
        bf16 hi = __float2bfloat16(v);
        bf16 lo = __float2bfloat16(v - __bfloat162float(hi));
        yr[i] = hi;
        yr[Dz + i] = lo;
    }
}

// ---------------- weight split: [K][N] fp32 -> [2K][N] bf16 [hi;lo] ------------
__global__ void convw_kernel(const float* __restrict__ src, bf16* __restrict__ dst,
                             int K, int logN) {
    unsigned nmask = (unsigned)((1 << logN) - 1);
    size_t total8 = ((size_t)K << logN) >> 3;
    for (size_t g = blockIdx.x * blockDim.x + threadIdx.x; g < total8;
         g += (size_t)gridDim.x * blockDim.x) {
        float4 a0 = ((const float4*)src)[g * 2];
        float4 a1 = ((const float4*)src)[g * 2 + 1];
        __align__(16) bf16 hv[8], lv[8];
        const float* f0 = (const float*)&a0;
        const float* f1 = (const float*)&a1;
#pragma unroll
        for (int q = 0; q < 4; q++) {
            bf16 hi = __float2bfloat16(f0[q]);
            hv[q] = hi;
            lv[q] = __float2bfloat16(f0[q] - __bfloat162float(hi));
        }
#pragma unroll
        for (int q = 0; q < 4; q++) {
            bf16 hi = __float2bfloat16(f1[q]);
            hv[4 + q] = hi;
            lv[4 + q] = __float2bfloat16(f1[q] - __bfloat162float(hi));
        }
        size_t base = g << 3;
        int k = (int)(base >> logN);
        int n = (int)(base & nmask);
        *(float4*)&dst[((size_t)k << logN) + n] = *(float4*)hv;
        *(float4*)&dst[((size_t)(K + k) << logN) + n] = *(float4*)lv;
    }
}

// ---------------- bf16 tensor-core GEMM (z-batched, 3-term remap, 3-stage) ------
// Logical C[M,N] = A[M,3*Kthird] x B[3*Kthird,N] stored [hi|lo] (2*Kthird);
// k-block kt maps: A-block = kt<KB?kt:kt-KB, B-block = kt<2KB?kt:kt-2KB.
// 128 threads, 4 warps, warp tile 64x64, CTA tile 128x128. 3-stage smem ring.
template<int EPI>
__global__ void __launch_bounds__(128, 2)
hgemm_kernel(const bf16* __restrict__ A, const bf16* __restrict__ B,
             float* __restrict__ Cf, bf16* __restrict__ Cb,
             int M, int N, int Kthird,
             const float* __restrict__ bias, const float* __restrict__ resid,
             const float* __restrict__ wdv,
             const int* __restrict__ elist, const int* __restrict__ ecnt,
             size_t a_zs, size_t b_zs, size_t c_zs, int bias_zs) {
    int z = blockIdx.z;
    int bm = blockIdx.y * 128, bn = blockIdx.x * 128;
    int cnt = M;
    if (ecnt) {
        cnt = ecnt[z];
        int padded = (cnt + 127) & ~127;
        if (bm >= padded) return;
    }
    A += (size_t)z * a_zs;
    B += (size_t)z * b_zs;
    if (bias) bias += (size_t)z * bias_zs;
    const int* lst = elist ? elist + (size_t)z * Tz : nullptr;

    extern __shared__ __align__(16) char dynsmem[];
    int tid = threadIdx.x;
    int warp = tid >> 5, lane = tid & 31;
    int wm = (warp & 1) * 64, wn = (warp >> 1) * 64;

    const int KB = Kthird >> 5;
    const int KT = 3 * KB;
    const int AS = 2 * Kthird;

    int arow = tid >> 2, acol = (tid & 3) * 8;
    int brow = tid >> 4, bcol = (tid & 15) * 8;
    const bf16* Ag[4];
#pragma unroll
    for (int j = 0; j < 4; j++) {
        int r = bm + arow + 32 * j;
        if (EPI == 2) r = lst[r];
        Ag[j] = A + (size_t)r * AS + acol;
    }
    const bf16* Bg = B + (size_t)brow * N + bn + bcol;

    float c[4][8][4];
#pragma unroll
    for (int mi = 0; mi < 4; mi++)
#pragma unroll
        for (int ni = 0; ni < 8; ni++)
#pragma unroll
            for (int j = 0; j < 4; j++) c[mi][ni][j] = 0.f;

    // issue helper offsets within a stage
    const uint32_t smem_base = smem_u32(dynsmem);
    uint32_t aoff = (uint32_t)(arow * 80 + acol * 2);           // As row stride 80B
    uint32_t boff = (uint32_t)(AS_BYTES + brow * 272 + bcol * 2); // Bs row stride 272B

    // prologue: tiles 0 and 1 into stages 0 and 1 (one group each)
    {
        uint32_t s0 = smem_base;
#pragma unroll
        for (int j = 0; j < 4; j++)
            CPA16(s0 + aoff + (uint32_t)(j * 32 * 80), Ag[j]);
#pragma unroll
        for (int j = 0; j < 4; j++)
            CPA16(s0 + boff + (uint32_t)(j * 8 * 272), Bg + (size_t)(8 * j) * N);
        CPA_COMMIT();
        uint32_t s1 = smem_base + STAGE_BYTES;
        int ak = 1, bk = 1;   // tile 1: always within first third remaps to 1
#pragma unroll
        for (int j = 0; j < 4; j++)
            CPA16(s1 + aoff + (uint32_t)(j * 32 * 80), Ag[j] + ak * 32);
#pragma unroll
        for (int j = 0; j < 4; j++)
            CPA16(s1 + boff + (uint32_t)(j * 8 * 272), Bg + (size_t)(bk * 32 + 8 * j) * N);
        CPA_COMMIT();
    }

    int buf = 0, nbuf = 2;
    for (int kt = 0; kt < KT; kt++) {
        if (kt + 1 < KT) { CPA_WAIT1(); } else { CPA_WAIT0(); }
        __syncthreads();
        if (kt + 2 < KT) {
            int k2 = kt + 2;
            int ak = (k2 < KB) ? k2 : k2 - KB;
            int bk = (k2 < 2 * KB) ? k2 : k2 - 2 * KB;
            uint32_t sb = smem_base + (uint32_t)nbuf * STAGE_BYTES;
#pragma unroll
            for (int j = 0; j < 4; j++)
                CPA16(sb + aoff + (uint32_t)(j * 32 * 80), Ag[j] + ak * 32);
#pragma unroll
            for (int j = 0; j < 4; j++)
                CPA16(sb + boff + (uint32_t)(j * 8 * 272),
                      Bg + (size_t)(bk * 32 + 8 * j) * N);
            CPA_COMMIT();
            nbuf = (nbuf == 2) ? 0 : nbuf + 1;
        }
        uint32_t cb = smem_base + (uint32_t)buf * STAGE_BYTES;
#pragma unroll
        for (int kk = 0; kk < 32; kk += 16) {
            uint32_t a[4][4], b[8][2];
#pragma unroll
            for (int mi = 0; mi < 4; mi++) {
                uint32_t addr = cb + (uint32_t)((wm + mi * 16 + (lane & 15)) * 80
                                   + (kk + ((lane >> 4) << 3)) * 2);
                ldsm4(a[mi][0], a[mi][1], a[mi][2], a[mi][3], addr);
            }
#pragma unroll
            for (int nj = 0; nj < 4; nj++) {
                uint32_t addr = cb + (uint32_t)(AS_BYTES + (kk + (lane & 15)) * 272
                                   + (wn + nj * 16 + ((lane >> 4) << 3)) * 2);
                ldsm4t(b[2 * nj][0], b[2 * nj][1], b[2 * nj + 1][0], b[2 * nj + 1][1], addr);
            }
#pragma unroll
            for (int mi = 0; mi < 4; mi++)
#pragma unroll
                for (int ni = 0; ni < 8; ni++)
                    mma_bf16(c[mi][ni], a[mi][0], a[mi][1], a[mi][2], a[mi][3],
                             b[ni][0], b[ni][1]);
        }
        buf = (buf == 2) ? 0 : buf + 1;
    }

#pragma unroll
    for (int mi = 0; mi < 4; mi++) {
#pragma unroll
        for (int rr = 0; rr < 2; rr++) {
            int r = bm + wm + mi * 16 + (lane >> 2) + rr * 8;
            if (EPI == 3) {
                if (r < cnt) {
                    int tok = lst[r];
                    float rsc = wdv[(size_t)tok * Ez + z];
                    float* dst = Cf + (size_t)z * c_zs;
#pragma unroll
                    for (int ni = 0; ni < 8; ni++)
#pragma unroll
                        for (int cc = 0; cc < 2; cc++) {
                            int col = bn + wn + ni * 8 + (lane & 3) * 2 + cc;
                            dst[(size_t)tok * N + col] =
                                rsc * (c[mi][ni][rr * 2 + cc] + bias[col]);
                        }
                }
            } else if (EPI == 5) {
                if (z == 0) {
#pragma unroll
                    for (int ni = 0; ni < 8; ni++)
#pragma unroll
                        for (int cc = 0; cc < 2; cc++) {
                            int col = bn + wn + ni * 8 + (lane & 3) * 2 + cc;
                            Cf[(size_t)r * N + col] = c[mi][ni][rr * 2 + cc];
                        }
                } else {
                    bf16* dst = Cb + (size_t)(z - 1) * c_zs;
#pragma unroll
                    for (int ni = 0; ni < 8; ni++) {
                        int colb = bn + wn + ni * 8 + (lane & 3) * 2;
                        __nv_bfloat162 p;
                        p.x = __float2bfloat16(c[mi][ni][rr * 2]);
                        p.y = __float2bfloat16(c[mi][ni][rr * 2 + 1]);
                        *(__nv_bfloat162*)&dst[(size_t)r * N + colb] = p;
                    }
                }
            } else if (EPI == 2) {
                bf16* dstb = Cb + (size_t)z * c_zs;
#pragma unroll
                for (int ni = 0; ni < 8; ni++)
#pragma unroll
                    for (int cc = 0; cc < 2; cc++) {
                        int col = bn + wn + ni * 8 + (lane & 3) * 2 + cc;
                        float g = gelu_f(c[mi][ni][rr * 2 + cc] + bias[col]);
                        bf16 hi = __float2bfloat16(g);
                        bf16 lo = __float2bfloat16(g - __bfloat162float(hi));
                        size_t base = (size_t)r * 2 * N;
                        dstb[base + col] = hi;
                        dstb[base + N + col] = lo;
                    }
            } else {
#pragma unroll
                for (int ni = 0; ni < 8; ni++)
#pragma unroll
                    for (int cc = 0; cc < 2; cc++) {
                        int col = bn + wn + ni * 8 + (lane & 3) * 2 + cc;
                        float val = c[mi][ni][rr * 2 + cc];
                        if (EPI == 0) Cf[(size_t)r * N + col] = val;
                        else          Cf[(size_t)r * N + col] = val + resid[(size_t)r * N + col];
                    }
            }
        }
    }
}

// ---------------- small fp32 GEMM (kI: N=64, wI: N=4) --------------------------
__global__ void __launch_bounds__(256, 2)
sgemm_small_kernel(const float* __restrict__ A, const float* __restrict__ B,
                   float* __restrict__ C, int M, int N, int K) {
    const int BM = 128, BN = 128, BK = 8, TM = 8, TN = 8;
    __shared__ float As[BK][BM];
    __shared__ float Bs[BK][BN];
    int tid = threadIdx.x;
    int bm = blockIdx.y * BM;
    int bn = blockIdx.x * BN;
    int trow = (tid / 16) * TM;
    int tcol = (tid % 16) * TN;
    float acc[TM][TN];
#pragma unroll
    for (int i = 0; i < TM; i++)
#pragma unroll
        for (int j = 0; j < TN; j++) acc[i][j] = 0.f;
    int arow = tid >> 1, acol = (tid & 1) * 4;
    int brow = tid >> 5, bcol = (tid & 31) * 4;
    const float* Aptr = A + (size_t)(bm + arow) * K;
    for (int k0 = 0; k0 < K; k0 += BK) {
        float4 av = *(const float4*)(Aptr + k0 + acol);
        As[acol + 0][arow] = av.x; As[acol + 1][arow] = av.y;
        As[acol + 2][arow] = av.z; As[acol + 3][arow] = av.w;
        int bc = bn + bcol;
#pragma unroll
        for (int j = 0; j < 4; j++)
            Bs[brow][bcol + j] = (bc + j < N) ? B[(size_t)(k0 + brow) * N + bc + j] : 0.f;
        __syncthreads();
#pragma unroll
        for (int kk = 0; kk < BK; kk++) {
            float ar[TM], br[TN];
#pragma unroll
            for (int i = 0; i < TM; i++) ar[i] = As[kk][trow + i];
#pragma unroll
            for (int j = 0; j < TN; j++) br[j] = Bs[kk][tcol + j];
#pragma unroll
            for (int i = 0; i < TM; i++)
#pragma unroll
                for (int j = 0; j < TN; j++) acc[i][j] += ar[i] * br[j];
        }
        __syncthreads();
    }
#pragma unroll
    for (int i = 0; i < TM; i++) {
        int r = bm + trow + i;
#pragma unroll
        for (int j = 0; j < TN; j++) {
            int cidx = bn + tcol + j;
            if (cidx < N) C[(size_t)r * N + cidx] = acc[i][j];
        }
    }
}

// ---------------- indexer scores ------------------------------------------------
__global__ void idxscore_kernel(const float* __restrict__ qI, const float* __restrict__ kI,
                                const float* __restrict__ wI, float* __restrict__ sc) {
    int b  = blockIdx.z;
    int t0 = blockIdx.y * 16;
    int s0 = blockIdx.x * 64;
    if (s0 > t0 + 15) return;
    __shared__ float qIs[16][257];
    __shared__ float kIs[64][65];
    __shared__ float wIs[16][4];
    int tx = threadIdx.x, ty = threadIdx.y;
    int tid = ty * 16 + tx;
    for (int idx = tid; idx < 16 * 256; idx += 256) {
        int r = idx >> 8, c = idx & 255;
        qIs[r][c] = qI[((size_t)(b * Sz + t0 + r)) * 256 + c];
    }
    for (int idx = tid; idx < 64 * 64; idx += 256) {
        int r = idx >> 6, c = idx & 63;
        kIs[r][c] = kI[((size_t)(b * Sz + s0 + r)) * 64 + c];
    }
    if (tid < 64) wIs[tid >> 2][tid & 3] = wI[((size_t)(b * Sz + (tid >> 2) + t0)) * 4 + (tid & 3)];
    __syncthreads();

    float acc4[4] = {0.f, 0.f, 0.f, 0.f};
#pragma unroll
    for (int h = 0; h < 4; h++) {
        float dot[4] = {0.f, 0.f, 0.f, 0.f};
#pragma unroll
        for (int d = 0; d < 64; d++) {
            float qv = qIs[ty][h * 64 + d];
            dot[0] += qv * kIs[tx +  0][d];
            dot[1] += qv * kIs[tx + 16][d];
            dot[2] += qv * kIs[tx + 32][d];
            dot[3] += qv * kIs[tx + 48][d];
        }
        float wv = wIs[ty][h];
#pragma unroll
        for (int j = 0; j < 4; j++) acc4[j] += wv * fmaxf(dot[j], 0.f);
    }
    int t = t0 + ty;
#pragma unroll
    for (int j = 0; j < 4; j++) {
        int s = s0 + tx + 16 * j;
        if (s <= t) sc[((size_t)(b * Sz + t)) * Sz + s] = acc4[j];
    }
}

// ---------------- top-k (512) per (b,t): radix select, jax tie-break -----------
__global__ void topk_kernel(const float* __restrict__ sc, int* __restrict__ selidx,
                            int* __restrict__ selcnt) {
    int bt = blockIdx.x;
    int t = bt & (Sz - 1);
    int n = t + 1;
    int tid = threadIdx.x;
    int* outp = selidx + (size_t)bt * TKz;
    if (n <= TKz) {
        for (int i = tid; i < n; i += 256) outp[i] = i;
        if (tid == 0) selcnt[bt] = n;
        return;
    }
    const float* row = sc + (size_t)bt * Sz;
    __shared__ unsigned keys[Sz];
    for (int i = tid; i < n; i += 256) {
        unsigned u = __float_as_uint(row[i]);
        keys[i] = (u & 0x80000000u) ? ~u : (u | 0x80000000u);
    }
    __shared__ int hist[256];
    __shared__ unsigned p_s;
    __shared__ int need_s;
    if (tid == 0) { p_s = 0; need_s = TKz; }
    __syncthreads();
    for (int byte = 3; byte >= 0; byte--) {
        int sh = byte * 8;
        for (int i = tid; i < 256; i += 256) hist[i] = 0;
        __syncthreads();
        unsigned p = p_s;
        unsigned mask_hi = (byte == 3) ? 0u : (0xFFFFFFFFu << (sh + 8));
        for (int i = tid; i < n; i += 256) {
            unsigned k = keys[i];
            if ((k & mask_hi) == p) atomicAdd(&hist[(k >> sh) & 255u], 1);
        }
        __syncthreads();
        if (tid == 0) {
            int need = need_s;
            int acc = 0;
            int chosen = 0;
            for (int b2 = 255; b2 >= 0; b2--) {
                if (acc + hist[b2] >= need) { chosen = b2; break; }
                acc += hist[b2];
            }
            need_s = need - acc;
            p_s = p | ((unsigned)chosen << sh);
        }
        __syncthreads();
    }
    unsigned p = p_s;   // exact TKz-th largest key
    __shared__ int pos;
    if (tid == 0) pos = 0;
    __syncthreads();
    for (int i = tid; i < n; i += 256)
        if (keys[i] > p) { int j = atomicAdd(&pos, 1); outp[j] = i; }
    __syncthreads();
    if (tid == 0) {
        int j = pos;
        for (int i = 0; i < n && j < TKz; i++)
            if (keys[i] == p) outp[j++] = i;
        selcnt[bt] = TKz;
    }
}

// ---------------- sparse attention (bf16 K/V), two-phase ------------------------
__global__ void __launch_bounds__(512)
attn_kernel(const float* __restrict__ q, const bf16* __restrict__ kb,
            const bf16* __restrict__ vb, const int* __restrict__ selidx,
            const int* __restrict__ selcnt, bf16* __restrict__ aox) {
    int bt = blockIdx.x;
    int b = bt >> 11;
    int tid = threadIdx.x;
    __shared__ float qs[Hz * DHz];
    __shared__ int sels[TKz + 4];
    __shared__ float sscore[Hz][TKz];
    int n = selcnt[bt];
    int n4 = (n + 3) & ~3;
    for (int i = tid; i < Dz; i += 512) qs[i] = q[(size_t)bt * Dz + i];
    for (int i = tid; i < n; i += 512) sels[i] = selidx[(size_t)bt * TKz + i];
    if (tid < 4) sels[n + tid] = selidx[(size_t)bt * TKz];   // pad with sel 0
    __syncthreads();
    int h = tid >> 5, lane = tid & 31;
    float q0 = qs[h * 64 + 2 * lane], q1 = qs[h * 64 + 2 * lane + 1];
    size_t hoff = h * 64 + 2 * lane;
    float m = -3.0e38f;
    for (int i = 0; i < n4; i += 4) {
        float part[4];
#pragma unroll
        for (int j = 0; j < 4; j++) {
            int s = sels[i + j];
            float2 kf = __bfloat1622float2(
                *(const __nv_bfloat162*)(kb + ((size_t)(b * Sz + s)) * Dz + hoff));
            part[j] = q0 * kf.x + q1 * kf.y;
        }
#pragma unroll
        for (int off = 16; off; off >>= 1)
#pragma unroll
            for (int j = 0; j < 4; j++)
                part[j] += __shfl_xor_sync(0xffffffffu, part[j], off);
#pragma unroll
        for (int j = 0; j < 4; j++) {
            float scv = part[j] * 0.125f;
            sscore[h][i + j] = scv;
            m = fmaxf(m, scv);
        }
    }
    float l = 0.f, o0 = 0.f, o1 = 0.f;
#pragma unroll 4
    for (int i = 0; i < n; i++) {
        float pw = __expf(sscore[h][i] - m);
        int s = sels[i];
        float2 vf = __bfloat1622float2(
            *(const __nv_bfloat162*)(vb + ((size_t)(b * Sz + s)) * Dz + hoff));
        o0 += pw * vf.x;
        o1 += pw * vf.y;
        l += pw;
    }
    float inv = 1.0f / l;
    o0 *= inv; o1 *= inv;
    size_t base = (size_t)bt * 2 * Dz;
    int c0 = h * 64 + 2 * lane, c1 = c0 + 1;
    bf16 h0 = __float2bfloat16(o0);
    bf16 l0 = __float2bfloat16(o0 - __bfloat162float(h0));
    bf16 h1 = __float2bfloat16(o1);
    bf16 l1 = __float2bfloat16(o1 - __bfloat162float(h1));
    aox[base + c0] = h0;       aox[base + c1] = h1;
    aox[base + Dz + c0] = l0;  aox[base + Dz + c1] = l1;
}

// ---------------- gate: softmax(4) + top-2 + combine weights -------------------
__global__ void gate_kernel(const float* __restrict__ xn2, const float* __restrict__ gw,
                            float* __restrict__ wdense, float* __restrict__ probsb) {
    int t = blockIdx.x;
    int tid = threadIdx.x;
    const float* xr = xn2 + (size_t)t * Dz;
    float le[4] = {0.f, 0.f, 0.f, 0.f};
    for (int d = tid; d < Dz; d += 256) {
        float xv = xr[d];
        const float* g = gw + (size_t)d * 4;
        le[0] += xv * g[0]; le[1] += xv * g[1];
        le[2] += xv * g[2]; le[3] += xv * g[3];
    }
    __shared__ float red[4][256];
    for (int e = 0; e < 4; e++) red[e][tid] = le[e];
    __syncthreads();
    for (int off = 128; off; off >>= 1) {
        if (tid < off)
            for (int e = 0; e < 4; e++) red[e][tid] += red[e][tid + off];
        __syncthreads();
    }
    if (tid == 0) {
        float lg[4], pr[4];
        float mx = -3.0e38f;
        for (int e = 0; e < 4; e++) { lg[e] = red[e][0]; mx = fmaxf(mx, lg[e]); }
        float sum = 0.f;
        for (int e = 0; e < 4; e++) { pr[e] = expf(lg[e] - mx); sum += pr[e]; }
        float inv = 1.0f / sum;
        for (int e = 0; e < 4; e++) { pr[e] *= inv; probsb[(size_t)t * 4 + e] = pr[e]; }
        int i1 = 0;
        for (int e = 1; e < 4; e++) if (pr[e] > pr[i1]) i1 = e;
        int i2 = -1; float b2v = -1.f;
        for (int e = 0; e < 4; e++) if (e != i1 && pr[e] > b2v) { b2v = pr[e]; i2 = e; }
        float wsum = pr[i1] + pr[i2];
        float wd[4] = {0.f, 0.f, 0.f, 0.f};
        wd[i1] = pr[i1] / wsum;
        wd[i2] = pr[i2] / wsum;
        for (int e = 0; e < 4; e++) wdense[(size_t)t * 4 + e] = wd[e];
    }
}

// ---------------- routing -------------------------------------------------------
__global__ void route_zero_kernel(int* __restrict__ ecnt) {
    if (threadIdx.x < Ez) ecnt[threadIdx.x] = 0;
}
__global__ void route_kernel(const float* __restrict__ wd, int* __restrict__ ecnt,
                             int* __restrict__ elist) {
    int t = blockIdx.x * blockDim.x + threadIdx.x;
    if (t < Tz) {
#pragma unroll
        for (int e = 0; e < Ez; e++)
            if (wd[(size_t)t * Ez + e] > 0.f) {
                int p = atomicAdd(&ecnt[e], 1);
                elist[e * Tz + p] = t;
            }
    }
}
__global__ void route_pad_kernel(const int* __restrict__ ecnt, int* __restrict__ elist) {
    int e = blockIdx.x;
    int cnt = ecnt[e];
    int padded = (cnt + 127) & ~127;
    for (int i = cnt + threadIdx.x; i < padded; i += blockDim.x) elist[e * Tz + i] = 0;
}

// ---------------- aux loss ------------------------------------------------------
__global__ void aux_kernel(const float* __restrict__ probsb, const float* __restrict__ wdense,
                           float* __restrict__ out_aux) {
    int tid = threadIdx.x;
    float sP[4] = {0.f, 0.f, 0.f, 0.f}, sF[4] = {0.f, 0.f, 0.f, 0.f};
    for (int t = tid; t < Tz; t += 256)
        for (int e = 0; e < 4; e++) {
            sP[e] += probsb[(size_t)t * 4 + e];
            sF[e] += (wdense[(size_t)t * 4 + e] > 0.f) ? 1.f : 0.f;
        }
    __shared__ float rP[4][256], rF[4][256];
    for (int e = 0; e < 4; e++) { rP[e][tid] = sP[e]; rF[e][tid] = sF[e]; }
    __syncthreads();
    for (int off = 128; off; off >>= 1) {
        if (tid < off)
            for (int e = 0; e < 4; e++) {
                rP[e][tid] += rP[e][tid + off];
                rF[e][tid] += rF[e][tid + off];
            }
        __syncthreads();
    }
    if (tid == 0) {
        float aux = 0.f;
        for (int e = 0; e < 4; e++)
            aux += (rF[e][0] * (1.0f / Tz)) * (rP[e][0] * (1.0f / Tz));
        *out_aux = (float)Ez * aux;
    }
}

// ---------------- final: out = x2 + sum_e masked ffe[e] -------------------------
__global__ void final_kernel(const float* __restrict__ x2, const float* __restrict__ ffe,
                             const float* __restrict__ wd, float* __restrict__ out) {
    for (int i = blockIdx.x * blockDim.x + threadIdx.x; i < Tz * Dz;
         i += gridDim.x * blockDim.x) {
        int t = i >> 10;
        float s = x2[i];
#pragma unroll
        for (int e = 0; e < Ez; e++)
            if (wd[(size_t)t * Ez + e] > 0.f) s += ffe[(size_t)e * Tz * Dz + i];
        out[i] = s;
    }
}

// ---------------- launch (multi-stream fork/join for graph capture) -------------
extern "C" void kernel_launch(void* const* d_in, const int* in_sizes, int n_in,
                              void* d_out, int out_size) {
    const float* x      = (const float*)d_in[0];
    const float* n1w    = (const float*)d_in[1];
    const float* n2w    = (const float*)d_in[2];
    const float* wq     = (const float*)d_in[3];
    const float* wk     = (const float*)d_in[4];
    const float* wv     = (const float*)d_in[5];
    const float* wo     = (const float*)d_in[6];
    const float* idx_wq = (const float*)d_in[7];
    const float* idx_wk = (const float*)d_in[8];
    const float* idx_ww = (const float*)d_in[9];
    const float* gate_w = (const float*)d_in[10];
    const float* w1     = (const float*)d_in[11];
    const float* b1     = (const float*)d_in[12];
    const float* w2     = (const float*)d_in[13];
    const float* b2     = (const float*)d_in[14];
    float* out = (float*)d_out;

    float *xn, *q, *qI, *kI, *wI, *sc, *x2, *xn2, *wd, *pr, *ffe;
    int *selidx, *selcnt, *ecnt, *elist;
    bf16 *kvb, *xnx, *xn2x, *aox, *hx, *wqkvx, *wox, *iwqx, *w1x, *w2x;
    cudaGetSymbolAddress((void**)&xn,  g_xn);
    cudaGetSymbolAddress((void**)&q,   g_q);
    cudaGetSymbolAddress((void**)&qI,  g_qI);
    cudaGetSymbolAddress((void**)&kI,  g_kI);
    cudaGetSymbolAddress((void**)&wI,  g_wI);
    cudaGetSymbolAddress((void**)&sc,  g_sc);
    cudaGetSymbolAddress((void**)&selidx, g_selidx);
    cudaGetSymbolAddress((void**)&selcnt, g_selcnt);
    cudaGetSymbolAddress((void**)&x2,  g_x2);
    cudaGetSymbolAddress((void**)&xn2, g_xn2);
    cudaGetSymbolAddress((void**)&wd,  g_wd);
    cudaGetSymbolAddress((void**)&pr,  g_pr);
    cudaGetSymbolAddress((void**)&ffe, g_ffe);
    cudaGetSymbolAddress((void**)&ecnt,  g_ecnt);
    cudaGetSymbolAddress((void**)&elist, g_elist);
    cudaGetSymbolAddress((void**)&kvb,  g_kvb);
    cudaGetSymbolAddress((void**)&xnx,  g_xnx);
    cudaGetSymbolAddress((void**)&xn2x, g_xn2x);
    cudaGetSymbolAddress((void**)&aox,  g_aox);
    cudaGetSymbolAddress((void**)&hx,   g_hx);
    cudaGetSymbolAddress((void**)&wqkvx, g_wqkvx);
    cudaGetSymbolAddress((void**)&wox,  g_wox);
    cudaGetSymbolAddress((void**)&iwqx, g_iwqx);
    cudaGetSymbolAddress((void**)&w1x,  g_w1x);
    cudaGetSymbolAddress((void**)&w2x,  g_w2x);

    static cudaStream_t s1 = nullptr, s2 = nullptr;
    static cudaEvent_t e0, e1, eTopk, eConv;
    if (!s1) {
        cudaStreamCreateWithFlags(&s1, cudaStreamNonBlocking);
        cudaStreamCreateWithFlags(&s2, cudaStreamNonBlocking);
        cudaEventCreateWithFlags(&e0, cudaEventDisableTiming);
        cudaEventCreateWithFlags(&e1, cudaEventDisableTiming);
        cudaEventCreateWithFlags(&eTopk, cudaEventDisableTiming);
        cudaEventCreateWithFlags(&eConv, cudaEventDisableTiming);
        cudaFuncSetAttribute(hgemm_kernel<0>, cudaFuncAttributeMaxDynamicSharedMemorySize, HG_SMEM);
        cudaFuncSetAttribute(hgemm_kernel<1>, cudaFuncAttributeMaxDynamicSharedMemorySize, HG_SMEM);
        cudaFuncSetAttribute(hgemm_kernel<2>, cudaFuncAttributeMaxDynamicSharedMemorySize, HG_SMEM);
        cudaFuncSetAttribute(hgemm_kernel<3>, cudaFuncAttributeMaxDynamicSharedMemorySize, HG_SMEM);
        cudaFuncSetAttribute(hgemm_kernel<5>, cudaFuncAttributeMaxDynamicSharedMemorySize, HG_SMEM);
    }

    const size_t WZ = (size_t)2 * Dz * Dz;

    // fork
    cudaEventRecord(e0, 0);
    cudaStreamWaitEvent(s1, e0, 0);
    cudaStreamWaitEvent(s2, e0, 0);

    // s1: MoE weight conversions (join before w1 GEMM)
    for (int e = 0; e < Ez; e++) {
        convw_kernel<<<2048, 256, 0, s1>>>(w1 + (size_t)e * Dz * DFz,
                                           w1x + (size_t)e * 2 * Dz * DFz, Dz, 12);
        convw_kernel<<<2048, 256, 0, s1>>>(w2 + (size_t)e * DFz * Dz,
                                           w2x + (size_t)e * 2 * DFz * Dz, DFz, 10);
    }
    cudaEventRecord(eConv, s1);

    // s0: attention weights + norm1
    convw_kernel<<<512, 256>>>(wq, wqkvx, Dz, 10);
    convw_kernel<<<512, 256>>>(wk, wqkvx + WZ, Dz, 10);
    convw_kernel<<<512, 256>>>(wv, wqkvx + 2 * WZ, Dz, 10);
    convw_kernel<<<512, 256>>>(wo, wox, Dz, 10);
    rmsnorm2_kernel<<<Tz, 256>>>(x, n1w, xn, xnx);
    cudaEventRecord(e1, 0);

    // s2: indexer chain (iwqx conv has no deps; rest needs norm1)
    convw_kernel<<<128, 256, 0, s2>>>(idx_wq, iwqx, Dz, 8);
    cudaStreamWaitEvent(s2, e1, 0);
    sgemm_small_kernel<<<dim3(1, 32), 256, 0, s2>>>(xn, idx_wk, kI, Tz, DIz, Dz);
    sgemm_small_kernel<<<dim3(1, 32), 256, 0, s2>>>(xn, idx_ww, wI, Tz, HIz, Dz);
    hgemm_kernel<0><<<dim3(2, 32), 128, HG_SMEM, s2>>>(xnx, iwqx, qI, nullptr,
                                                 Tz, HIz * DIz, Dz,
                                                 nullptr, nullptr, nullptr, nullptr,
                                                 nullptr, 0, 0, 0, 0);
    idxscore_kernel<<<dim3(Sz / 64, Sz / 16, Bz), dim3(16, 16), 0, s2>>>(qI, kI, wI, sc);
    topk_kernel<<<Tz, 256, 0, s2>>>(sc, selidx, selcnt);
    cudaEventRecord(eTopk, s2);

    // s0: QKV (overlaps the s2 chain), then join for attention
    hgemm_kernel<5><<<dim3(8, 32, 3), 128, HG_SMEM>>>(xnx, wqkvx, q, kvb, Tz, Dz, Dz,
                                             nullptr, nullptr, nullptr, nullptr, nullptr,
                                             0, WZ, (size_t)Tz * Dz, 0);
    cudaStreamWaitEvent(0, eTopk, 0);
    attn_kernel<<<Tz, 512>>>(q, kvb, kvb + (size_t)Tz * Dz, selidx, selcnt, aox);
    hgemm_kernel<1><<<dim3(8, 32), 128, HG_SMEM>>>(aox, wox, x2, nullptr, Tz, Dz, Dz,
                                          nullptr, x, nullptr, nullptr, nullptr,
                                          0, 0, 0, 0);

    // ---- MoE path (routed + expert-batched) ----
    rmsnorm2_kernel<<<Tz, 256>>>(x2, n2w, xn2, xn2x);
    gate_kernel<<<Tz, 256>>>(xn2, gate_w, wd, pr);
    route_zero_kernel<<<1, 32>>>(ecnt);
    route_kernel<<<Tz / 256, 256>>>(wd, ecnt, elist);
    route_pad_kernel<<<Ez, 128>>>(ecnt, elist);
    cudaStreamWaitEvent(0, eConv, 0);
    hgemm_kernel<2><<<dim3(32, 32, Ez), 128, HG_SMEM>>>(xn2x, w1x, nullptr, hx, Tz, DFz, Dz,
                                               b1, nullptr, nullptr, elist, ecnt,
                                               0, (size_t)2 * Dz * DFz,
                                               (size_t)Tz * 2 * DFz, DFz);
    hgemm_kernel<3><<<dim3(8, 32, Ez), 128, HG_SMEM>>>(hx, w2x, ffe, nullptr, Tz, Dz, DFz,
                                              b2, nullptr, wd, elist, ecnt,
                                              (size_t)Tz * 2 * DFz, (size_t)2 * DFz * Dz,
                                              (size_t)Tz * Dz, Dz);

    final_kernel<<<8192, 256>>>(x2, ffe, wd, out);
    aux_kernel<<<1, 256>>>(pr, wd, out + (out_size - 1));
}